// round 1
// baseline (speedup 1.0000x reference)
#include <cuda_runtime.h>
#include <math.h>

#define MROWS 18432
#define TAU_INV 20.0f

// Scratch (alloc-free: device globals)
__device__ __align__(16) float g_xvis1[(size_t)MROWS * 512];
__device__ __align__(16) float g_concat[(size_t)MROWS * 388];
__device__ __align__(16) float g_act3[(size_t)MROWS * 256];
__device__ __align__(16) float g_logits[(size_t)MROWS * 36];

// ---------------------------------------------------------------------------
// Generic fused GEMM: C[M,N] = act(A[M,K] @ W[N,K]^T + bias), row-major,
// arbitrary lda/ldc (A and C may be column slices of wider buffers).
// Tile: 128x128x8, 256 threads, 8x8 per-thread micro-tile, register prefetch.
// ACT: 0 = relu, 1 = tanh
// ---------------------------------------------------------------------------
template <int ACT>
__global__ __launch_bounds__(256, 2) void gemm_bias_act(
    const float* __restrict__ A, int lda,
    const float* __restrict__ W,            // [N,K]
    const float* __restrict__ bias,         // [N]
    float* __restrict__ C, int ldc,
    int M, int N, int K)
{
    __shared__ float As[8][128];
    __shared__ float Bs[8][128];

    const int tid = threadIdx.x;
    const int tx = tid & 15;      // n block (8 cols each)
    const int ty = tid >> 4;      // m block (8 rows each)
    const int bm = blockIdx.y * 128;
    const int bn = blockIdx.x * 128;

    // global-load mapping: one float4 of A and one of W per thread per K-tile
    const int lm = tid >> 1;            // 0..127 (row within tile)
    const int lk = (tid & 1) << 2;      // 0 or 4

    float acc[8][8];
#pragma unroll
    for (int i = 0; i < 8; i++)
#pragma unroll
        for (int j = 0; j < 8; j++) acc[i][j] = 0.0f;

    const int nT = (K + 7) >> 3;

    float4 aNew = make_float4(0.f, 0.f, 0.f, 0.f);
    float4 bNew = make_float4(0.f, 0.f, 0.f, 0.f);

    // prefetch tile 0
    {
        const int k = lk;
        const int m = bm + lm;
        if (m < M) {
            if (k + 3 < K) {
                aNew = *(const float4*)(A + (size_t)m * lda + k);
            } else {
                float t0 = (k + 0 < K) ? A[(size_t)m * lda + k + 0] : 0.f;
                float t1 = (k + 1 < K) ? A[(size_t)m * lda + k + 1] : 0.f;
                float t2 = (k + 2 < K) ? A[(size_t)m * lda + k + 2] : 0.f;
                float t3 = (k + 3 < K) ? A[(size_t)m * lda + k + 3] : 0.f;
                aNew = make_float4(t0, t1, t2, t3);
            }
        }
        const int n = bn + lm;
        if (n < N) {
            if (k + 3 < K) {
                bNew = *(const float4*)(W + (size_t)n * K + k);
            } else {
                float t0 = (k + 0 < K) ? W[(size_t)n * K + k + 0] : 0.f;
                float t1 = (k + 1 < K) ? W[(size_t)n * K + k + 1] : 0.f;
                float t2 = (k + 2 < K) ? W[(size_t)n * K + k + 2] : 0.f;
                float t3 = (k + 3 < K) ? W[(size_t)n * K + k + 3] : 0.f;
                bNew = make_float4(t0, t1, t2, t3);
            }
        }
    }

    for (int t = 0; t < nT; ++t) {
        // stage current tile to smem
        As[lk + 0][lm] = aNew.x;
        As[lk + 1][lm] = aNew.y;
        As[lk + 2][lm] = aNew.z;
        As[lk + 3][lm] = aNew.w;
        Bs[lk + 0][lm] = bNew.x;
        Bs[lk + 1][lm] = bNew.y;
        Bs[lk + 2][lm] = bNew.z;
        Bs[lk + 3][lm] = bNew.w;
        __syncthreads();

        // prefetch next tile into registers (overlaps with FFMA below)
        if (t + 1 < nT) {
            const int k = (t + 1) * 8 + lk;
            const int m = bm + lm;
            aNew = make_float4(0.f, 0.f, 0.f, 0.f);
            bNew = make_float4(0.f, 0.f, 0.f, 0.f);
            if (m < M) {
                if (k + 3 < K) {
                    aNew = *(const float4*)(A + (size_t)m * lda + k);
                } else {
                    float t0 = (k + 0 < K) ? A[(size_t)m * lda + k + 0] : 0.f;
                    float t1 = (k + 1 < K) ? A[(size_t)m * lda + k + 1] : 0.f;
                    float t2 = (k + 2 < K) ? A[(size_t)m * lda + k + 2] : 0.f;
                    float t3 = (k + 3 < K) ? A[(size_t)m * lda + k + 3] : 0.f;
                    aNew = make_float4(t0, t1, t2, t3);
                }
            }
            const int n = bn + lm;
            if (n < N) {
                if (k + 3 < K) {
                    bNew = *(const float4*)(W + (size_t)n * K + k);
                } else {
                    float t0 = (k + 0 < K) ? W[(size_t)n * K + k + 0] : 0.f;
                    float t1 = (k + 1 < K) ? W[(size_t)n * K + k + 1] : 0.f;
                    float t2 = (k + 2 < K) ? W[(size_t)n * K + k + 2] : 0.f;
                    float t3 = (k + 3 < K) ? W[(size_t)n * K + k + 3] : 0.f;
                    bNew = make_float4(t0, t1, t2, t3);
                }
            }
        }

#pragma unroll
        for (int kk = 0; kk < 8; ++kk) {
            float4 a0 = *(const float4*)&As[kk][ty * 8];
            float4 a1 = *(const float4*)&As[kk][ty * 8 + 4];
            float4 b0 = *(const float4*)&Bs[kk][tx * 8];
            float4 b1 = *(const float4*)&Bs[kk][tx * 8 + 4];
            float a[8] = {a0.x, a0.y, a0.z, a0.w, a1.x, a1.y, a1.z, a1.w};
            float b[8] = {b0.x, b0.y, b0.z, b0.w, b1.x, b1.y, b1.z, b1.w};
#pragma unroll
            for (int i = 0; i < 8; i++)
#pragma unroll
                for (int j = 0; j < 8; j++)
                    acc[i][j] = fmaf(a[i], b[j], acc[i][j]);
        }
        __syncthreads();
    }

    // epilogue: bias + activation, guarded store
#pragma unroll
    for (int i = 0; i < 8; i++) {
        const int m = bm + ty * 8 + i;
        if (m >= M) continue;
#pragma unroll
        for (int j = 0; j < 8; j++) {
            const int n = bn + tx * 8 + j;
            if (n >= N) continue;
            float v = acc[i][j] + bias[n];
            if (ACT == 0) v = fmaxf(v, 0.0f);
            else          v = tanhf(v);
            C[(size_t)m * ldc + n] = v;
        }
    }
}

// relu(seq[:, :, 2560:2564]) -> concat cols [256,260)
__global__ void pos_relu_kernel(const float* __restrict__ seq,
                                float* __restrict__ concat)
{
    int i = blockIdx.x * blockDim.x + threadIdx.x;
    if (i < MROWS * 4) {
        int m = i >> 2;
        int j = i & 3;
        float v = seq[(size_t)m * 3076 + 2560 + j];
        concat[(size_t)m * 388 + 256 + j] = fmaxf(v, 0.0f);
    }
}

// Sinkhorn: per-batch 36x36 matrix, x=exp(x/TAU); 20x (row-LSE sub, col-LSE sub); exp.
__global__ __launch_bounds__(512) void sinkhorn_kernel(
    const float* __restrict__ logits, float* __restrict__ out)
{
    __shared__ float X[36][37];
    __shared__ float red[36];

    const int b = blockIdx.x;
    const int t = threadIdx.x;
    const float* src = logits + (size_t)b * 1296;

    for (int i = t; i < 1296; i += 512)
        X[i / 36][i % 36] = expf(src[i] * TAU_INV);
    __syncthreads();

    for (int it = 0; it < 20; ++it) {
        // row logsumexp
        if (t < 36) {
            float mx = -INFINITY;
#pragma unroll
            for (int c = 0; c < 36; c++) mx = fmaxf(mx, X[t][c]);
            float s = 0.0f;
#pragma unroll
            for (int c = 0; c < 36; c++) s += expf(X[t][c] - mx);
            red[t] = mx + logf(s);
        }
        __syncthreads();
        for (int i = t; i < 1296; i += 512) X[i / 36][i % 36] -= red[i / 36];
        __syncthreads();

        // col logsumexp
        if (t < 36) {
            float mx = -INFINITY;
#pragma unroll
            for (int r = 0; r < 36; r++) mx = fmaxf(mx, X[r][t]);
            float s = 0.0f;
#pragma unroll
            for (int r = 0; r < 36; r++) s += expf(X[r][t] - mx);
            red[t] = mx + logf(s);
        }
        __syncthreads();
        for (int i = t; i < 1296; i += 512) X[i / 36][i % 36] -= red[i % 36];
        __syncthreads();
    }

    for (int i = t; i < 1296; i += 512)
        out[(size_t)b * 1296 + i] = expf(X[i / 36][i % 36]);
}

extern "C" void kernel_launch(void* const* d_in, const int* in_sizes, int n_in,
                              void* d_out, int out_size)
{
    const float* seq    = (const float*)d_in[0];
    const float* W1t_w  = (const float*)d_in[1];
    const float* W1t_b  = (const float*)d_in[2];
    const float* W1v_w  = (const float*)d_in[3];
    const float* W1v_b  = (const float*)d_in[4];
    const float* W2v_w  = (const float*)d_in[5];
    const float* W2v_b  = (const float*)d_in[6];
    const float* W1s_w  = (const float*)d_in[7];
    const float* W1s_b  = (const float*)d_in[8];
    const float* Wfp_w  = (const float*)d_in[9];
    const float* Wfp_b  = (const float*)d_in[10];
    const float* Wfc_w  = (const float*)d_in[11];
    const float* Wfc_b  = (const float*)d_in[12];
    float* out = (float*)d_out;

    float *xvis1, *concat, *act3, *logits;
    cudaGetSymbolAddress((void**)&xvis1,  g_xvis1);
    cudaGetSymbolAddress((void**)&concat, g_concat);
    cudaGetSymbolAddress((void**)&act3,   g_act3);
    cudaGetSymbolAddress((void**)&logits, g_logits);

    const int M = MROWS;
    dim3 blk(256);
    const int mT = M / 128;   // 144

    // txt: 512 -> 128, into concat cols [0,128)
    gemm_bias_act<0><<<dim3(1, mT), blk>>>(seq, 3076, W1t_w, W1t_b,
                                           concat, 388, M, 128, 512);
    // vis layer 1: 2048 -> 512
    gemm_bias_act<0><<<dim3(4, mT), blk>>>(seq + 512, 3076, W1v_w, W1v_b,
                                           xvis1, 512, M, 512, 2048);
    // vis layer 2: 512 -> 128, into concat cols [128,256)
    gemm_bias_act<0><<<dim3(1, mT), blk>>>(xvis1, 512, W2v_w, W2v_b,
                                           concat + 128, 388, M, 128, 512);
    // sen: 512 -> 128, into concat cols [260,388)
    gemm_bias_act<0><<<dim3(1, mT), blk>>>(seq + 2564, 3076, W1s_w, W1s_b,
                                           concat + 260, 388, M, 128, 512);
    // pos: relu copy into concat cols [256,260)
    pos_relu_kernel<<<(M * 4 + 255) / 256, 256>>>(seq, concat);

    // fc_pos: 388 -> 256
    gemm_bias_act<0><<<dim3(2, mT), blk>>>(concat, 388, Wfp_w, Wfp_b,
                                           act3, 256, M, 256, 388);
    // fc: 256 -> 36, tanh
    gemm_bias_act<1><<<dim3(1, mT), blk>>>(act3, 256, Wfc_w, Wfc_b,
                                           logits, 36, M, 36, 256);

    // Sinkhorn, one CTA per batch matrix
    sinkhorn_kernel<<<512, 512>>>(logits, out);
}

// round 2
// speedup vs baseline: 1.3949x; 1.3949x over previous
#include <cuda_runtime.h>
#include <math.h>

#define MROWS 18432
#define TAU_INV 20.0f

typedef unsigned long long u64;

// Scratch (alloc-free: device globals)
__device__ __align__(16) float g_xvis1[(size_t)MROWS * 512];
__device__ __align__(16) float g_concat[(size_t)MROWS * 388];
__device__ __align__(16) float g_act3[(size_t)MROWS * 256];
__device__ __align__(16) float g_logits[(size_t)MROWS * 36];

// packed fp32x2 FMA: d = a * b + d (lanewise on [lo,hi])
#define FMA2(d, a, b) \
    asm("fma.rn.f32x2 %0, %1, %2, %0;" : "+l"(d) : "l"(a), "l"(b))

__device__ __forceinline__ float2 unpack2(u64 v) {
    float2 f;
    asm("mov.b64 {%0, %1}, %2;" : "=f"(f.x), "=f"(f.y) : "l"(v));
    return f;
}

__device__ __forceinline__ float4 load4_guard(const float* __restrict__ row, int k, int K) {
    if (k + 3 < K) return *(const float4*)(row + k);
    float4 r = make_float4(0.f, 0.f, 0.f, 0.f);
    if (k + 0 < K) r.x = row[k + 0];
    if (k + 1 < K) r.y = row[k + 1];
    if (k + 2 < K) r.z = row[k + 2];
    return r;
}

// ---------------------------------------------------------------------------
// GEMM body: C[128 x 128 tile] = act(A[M,K] @ W[N,K]^T + bias)
// 256 threads, 8x8 micro-tile computed as 8x(4 packed f32x2) via FFMA2.
// A tile stored pair-duplicated in smem so packed broadcasts come from LDS.
// M is assumed tile-exact (18432 = 144*128). N may be < 128 (fc: N=36), even.
// ACT: 0 = relu, 1 = tanh
// ---------------------------------------------------------------------------
template <int ACT>
__device__ __forceinline__ void gemm_body(
    const float* __restrict__ A, int lda,
    const float* __restrict__ W,            // [N,K]
    const float* __restrict__ bias,         // [N]
    float* __restrict__ C, int ldc,
    int N, int K, int bm, int bn,
    float (&As2)[8][260], float (&Bs)[8][132])
{
    const int tid = threadIdx.x;
    const int tx = tid & 15;      // n block (8 cols = 4 pairs)
    const int ty = tid >> 4;      // m block (8 rows)
    const int lm = tid >> 1;      // 0..127
    const int lk = (tid & 1) << 2;

    u64 acc2[8][4];
#pragma unroll
    for (int i = 0; i < 8; i++)
#pragma unroll
        for (int j = 0; j < 4; j++) acc2[i][j] = 0ull;

    const int nT = (K + 7) >> 3;
    const float* Arow = A + (size_t)(bm + lm) * lda;
    const float* Wrow = W + (size_t)(bn + lm) * K;
    const bool wvalid = (bn + lm) < N;

    float4 aN = load4_guard(Arow, lk, K);
    float4 bN = wvalid ? load4_guard(Wrow, lk, K) : make_float4(0.f, 0.f, 0.f, 0.f);

    for (int t = 0; t < nT; ++t) {
        // stage: A pair-duplicated, B plain
        *(float2*)&As2[lk + 0][2 * lm] = make_float2(aN.x, aN.x);
        *(float2*)&As2[lk + 1][2 * lm] = make_float2(aN.y, aN.y);
        *(float2*)&As2[lk + 2][2 * lm] = make_float2(aN.z, aN.z);
        *(float2*)&As2[lk + 3][2 * lm] = make_float2(aN.w, aN.w);
        Bs[lk + 0][lm] = bN.x;
        Bs[lk + 1][lm] = bN.y;
        Bs[lk + 2][lm] = bN.z;
        Bs[lk + 3][lm] = bN.w;
        __syncthreads();

        if (t + 1 < nT) {
            const int k = (t + 1) * 8 + lk;
            aN = load4_guard(Arow, k, K);
            bN = wvalid ? load4_guard(Wrow, k, K) : make_float4(0.f, 0.f, 0.f, 0.f);
        }

#pragma unroll
        for (int kk = 0; kk < 8; ++kk) {
            const float* ar = &As2[kk][ty * 16];
            const float* br = &Bs[kk][tx * 8];
            ulonglong2 A01 = *(const ulonglong2*)(ar + 0);
            ulonglong2 A23 = *(const ulonglong2*)(ar + 4);
            ulonglong2 A45 = *(const ulonglong2*)(ar + 8);
            ulonglong2 A67 = *(const ulonglong2*)(ar + 12);
            ulonglong2 B03 = *(const ulonglong2*)(br + 0);
            ulonglong2 B47 = *(const ulonglong2*)(br + 4);
            u64 a[8] = {A01.x, A01.y, A23.x, A23.y, A45.x, A45.y, A67.x, A67.y};
            u64 b[4] = {B03.x, B03.y, B47.x, B47.y};
#pragma unroll
            for (int i = 0; i < 8; i++)
#pragma unroll
                for (int j = 0; j < 4; j++)
                    FMA2(acc2[i][j], a[i], b[j]);
        }
        __syncthreads();
    }

    // epilogue: bias + activation, paired stores (all N are even)
#pragma unroll
    for (int i = 0; i < 8; i++) {
        const int m = bm + ty * 8 + i;
        float* crow = C + (size_t)m * ldc;
#pragma unroll
        for (int j = 0; j < 4; j++) {
            const int n = bn + tx * 8 + 2 * j;
            if (n < N) {
                float2 v = unpack2(acc2[i][j]);
                float r0 = v.x + bias[n];
                float r1 = v.y + bias[n + 1];
                if (ACT == 0) { r0 = fmaxf(r0, 0.f); r1 = fmaxf(r1, 0.f); }
                else          { r0 = tanhf(r0);      r1 = tanhf(r1); }
                *(float2*)(crow + n) = make_float2(r0, r1);
            }
        }
    }
}

template <int ACT>
__global__ __launch_bounds__(256, 2) void gemm_bias_act(
    const float* __restrict__ A, int lda,
    const float* __restrict__ W,
    const float* __restrict__ bias,
    float* __restrict__ C, int ldc,
    int N, int K)
{
    __shared__ float As2[8][260];
    __shared__ float Bs[8][132];
    gemm_body<ACT>(A, lda, W, bias, C, ldc, N, K,
                   blockIdx.y * 128, blockIdx.x * 128, As2, Bs);
}

// two independent N=128 GEMMs batched over blockIdx.z (txt + sen)
__global__ __launch_bounds__(256, 2) void gemm_dual(
    const float* __restrict__ A0, const float* __restrict__ W0,
    const float* __restrict__ b0, float* __restrict__ C0,
    const float* __restrict__ A1, const float* __restrict__ W1,
    const float* __restrict__ b1, float* __restrict__ C1,
    int lda, int ldc, int N, int K)
{
    __shared__ float As2[8][260];
    __shared__ float Bs[8][132];
    const float* A = blockIdx.z ? A1 : A0;
    const float* W = blockIdx.z ? W1 : W0;
    const float* b = blockIdx.z ? b1 : b0;
    float*       C = blockIdx.z ? C1 : C0;
    gemm_body<0>(A, lda, W, b, C, ldc, N, K, blockIdx.y * 128, 0, As2, Bs);
}

// relu(seq[:, :, 2560:2564]) -> concat cols [256,260)
__global__ void pos_relu_kernel(const float* __restrict__ seq,
                                float* __restrict__ concat)
{
    int i = blockIdx.x * blockDim.x + threadIdx.x;
    if (i < MROWS * 4) {
        int m = i >> 2;
        int j = i & 3;
        float v = seq[(size_t)m * 3076 + 2560 + j];
        concat[(size_t)m * 388 + 256 + j] = fmaxf(v, 0.0f);
    }
}

// Sinkhorn: per-batch 36x36 matrix, x=exp(x/TAU); 20x (row-LSE sub, col-LSE sub); exp.
__global__ __launch_bounds__(512) void sinkhorn_kernel(
    const float* __restrict__ logits, float* __restrict__ out)
{
    __shared__ float X[36][37];
    __shared__ float red[36];

    const int b = blockIdx.x;
    const int t = threadIdx.x;
    const float* src = logits + (size_t)b * 1296;

    for (int i = t; i < 1296; i += 512)
        X[i / 36][i % 36] = expf(src[i] * TAU_INV);
    __syncthreads();

    for (int it = 0; it < 20; ++it) {
        if (t < 36) {
            float mx = -INFINITY;
#pragma unroll
            for (int c = 0; c < 36; c++) mx = fmaxf(mx, X[t][c]);
            float s = 0.0f;
#pragma unroll
            for (int c = 0; c < 36; c++) s += expf(X[t][c] - mx);
            red[t] = mx + logf(s);
        }
        __syncthreads();
        for (int i = t; i < 1296; i += 512) X[i / 36][i % 36] -= red[i / 36];
        __syncthreads();

        if (t < 36) {
            float mx = -INFINITY;
#pragma unroll
            for (int r = 0; r < 36; r++) mx = fmaxf(mx, X[r][t]);
            float s = 0.0f;
#pragma unroll
            for (int r = 0; r < 36; r++) s += expf(X[r][t] - mx);
            red[t] = mx + logf(s);
        }
        __syncthreads();
        for (int i = t; i < 1296; i += 512) X[i / 36][i % 36] -= red[i % 36];
        __syncthreads();
    }

    for (int i = t; i < 1296; i += 512)
        out[(size_t)b * 1296 + i] = expf(X[i / 36][i % 36]);
}

extern "C" void kernel_launch(void* const* d_in, const int* in_sizes, int n_in,
                              void* d_out, int out_size)
{
    const float* seq    = (const float*)d_in[0];
    const float* W1t_w  = (const float*)d_in[1];
    const float* W1t_b  = (const float*)d_in[2];
    const float* W1v_w  = (const float*)d_in[3];
    const float* W1v_b  = (const float*)d_in[4];
    const float* W2v_w  = (const float*)d_in[5];
    const float* W2v_b  = (const float*)d_in[6];
    const float* W1s_w  = (const float*)d_in[7];
    const float* W1s_b  = (const float*)d_in[8];
    const float* Wfp_w  = (const float*)d_in[9];
    const float* Wfp_b  = (const float*)d_in[10];
    const float* Wfc_w  = (const float*)d_in[11];
    const float* Wfc_b  = (const float*)d_in[12];
    float* out = (float*)d_out;

    float *xvis1, *concat, *act3, *logits;
    cudaGetSymbolAddress((void**)&xvis1,  g_xvis1);
    cudaGetSymbolAddress((void**)&concat, g_concat);
    cudaGetSymbolAddress((void**)&act3,   g_act3);
    cudaGetSymbolAddress((void**)&logits, g_logits);

    dim3 blk(256);
    const int mT = MROWS / 128;   // 144

    // vis layer 1: 2048 -> 512 (the big one; no deps)
    gemm_bias_act<0><<<dim3(4, mT), blk>>>(seq + 512, 3076, W1v_w, W1v_b,
                                           xvis1, 512, 512, 2048);
    // txt (512->128, concat[:,0:128)) + sen (512->128, concat[:,260:388)) batched
    gemm_dual<<<dim3(1, mT, 2), blk>>>(seq, W1t_w, W1t_b, concat,
                                       seq + 2564, W1s_w, W1s_b, concat + 260,
                                       3076, 388, 128, 512);
    // pos: relu copy into concat cols [256,260)
    pos_relu_kernel<<<(MROWS * 4 + 255) / 256, 256>>>(seq, concat);
    // vis layer 2: 512 -> 128, into concat cols [128,256)
    gemm_bias_act<0><<<dim3(1, mT), blk>>>(xvis1, 512, W2v_w, W2v_b,
                                           concat + 128, 388, 128, 512);
    // fc_pos: 388 -> 256
    gemm_bias_act<0><<<dim3(2, mT), blk>>>(concat, 388, Wfp_w, Wfp_b,
                                           act3, 256, 256, 388);
    // fc: 256 -> 36, tanh
    gemm_bias_act<1><<<dim3(1, mT), blk>>>(act3, 256, Wfc_w, Wfc_b,
                                           logits, 36, 36, 256);

    // Sinkhorn, one CTA per batch matrix
    sinkhorn_kernel<<<512, 512>>>(logits, out);
}

// round 10
// speedup vs baseline: 1.7455x; 1.2513x over previous
#include <cuda_runtime.h>
#include <cuda_bf16.h>
#include <math.h>
#include <stdint.h>

#define MROWS 18432
#define TAU_INV 20.0f

typedef __nv_bfloat16 bf16;

// ---------------- scratch (device globals; alloc-free) ----------------
// 3 bf16 planes (h, m, l) per tensor: v == h + m + l exactly (to 2^-27)
#define SEQC 3072
__device__ __align__(128) bf16 g_seqP[3][(size_t)MROWS * SEQC];
__device__ __align__(128) bf16 g_xvP [3][(size_t)MROWS * 512];
__device__ __align__(128) bf16 g_ccP [3][(size_t)MROWS * 448];
__device__ __align__(128) bf16 g_a3P [3][(size_t)MROWS * 256];
__device__ __align__(128) bf16 g_wP  [3][128*512 + 512*2048 + 128*512 + 128*512 + 256*448 + 36*256];
__device__ __align__(128) float g_logits[(size_t)MROWS * 36];

#define WOFF_TXT   0
#define WOFF_VIS1  (WOFF_TXT  + 128*512)
#define WOFF_VIS2  (WOFF_VIS1 + 512*2048)
#define WOFF_SEN   (WOFF_VIS2 + 128*512)
#define WOFF_FCP   (WOFF_SEN  + 128*512)
#define WOFF_FC    (WOFF_FCP  + 256*448)

// ---------------- smem layout ----------------
// row: 32 data bf16 (64B) + 8 pad = 80B, conflict-free ldmatrix.
#define ROWB    80
#define A_PLANE (128 * ROWB)           // 10240
#define W_PLANE (64 * ROWB)            // 5120
#define W_OFF   (3 * A_PLANE)          // 30720
#define STAGE_B (3 * A_PLANE + 3 * W_PLANE)   // 46080
#define NSTG    3
#define GEMM_SMEM (NSTG * STAGE_B)     // 138240

// ---------------- PTX helpers ----------------
__device__ __forceinline__ uint32_t smem_u32(const void* p) {
    uint32_t a;
    asm("{ .reg .u64 t; cvta.to.shared.u64 t, %1; cvt.u32.u64 %0, t; }" : "=r"(a) : "l"(p));
    return a;
}

#define CPA(dst, src, pb) \
    asm volatile("cp.async.cg.shared.global [%0], [%1], 16, %2;" \
                 :: "r"(dst), "l"(src), "r"(pb) : "memory")
#define CPA_COMMIT() asm volatile("cp.async.commit_group;" ::: "memory")
#define CPA_WAIT2()  asm volatile("cp.async.wait_group 2;" ::: "memory")

#define LDSM4(r0, r1, r2, r3, a) \
    asm volatile("ldmatrix.sync.aligned.m8n8.x4.shared.b16 {%0,%1,%2,%3}, [%4];" \
                 : "=r"(r0), "=r"(r1), "=r"(r2), "=r"(r3) : "r"(a))

#define MMAB(d, a, b) \
    asm volatile("mma.sync.aligned.m16n8k16.row.col.f32.bf16.bf16.f32 " \
                 "{%0,%1,%2,%3}, {%4,%5,%6,%7}, {%8,%9}, {%0,%1,%2,%3};" \
                 : "+f"((d)[0]), "+f"((d)[1]), "+f"((d)[2]), "+f"((d)[3]) \
                 : "r"((a)[0]), "r"((a)[1]), "r"((a)[2]), "r"((a)[3]), \
                   "r"((b)[0]), "r"((b)[1]))

// exact 3-way bf16 split: v == h + m + l + O(2^-27 v)
__device__ __forceinline__ void bf16_split3(float v, bf16& h, bf16& m, bf16& l) {
    h = __float2bfloat16(v);
    const float r1 = v - __bfloat162float(h);    // exact
    m = __float2bfloat16(r1);
    l = __float2bfloat16(r1 - __bfloat162float(m));
}

// ---------------- GEMM: C[M,N] = act(A[M,K] @ W[N,K]^T + bias) ----------------
// A, W given as 3 bf16 planes. 6-term emulation with dual accumulators:
//   acc_main = sum hh ;  acc_small = sum(hm+mh+hl+lh+mm) ;  final = main+small
// CTA tile 128x64, 8 warps (2x4), warp tile 64x16. M tile-exact.
// OUTMODE 0: relu -> 3 bf16 planes. OUTMODE 1: tanh -> fp32 (col guard).
template <int OUTMODE>
__global__ __launch_bounds__(256, 1) void gemm_bf6(
    const bf16* __restrict__ Ah, const bf16* __restrict__ Am, const bf16* __restrict__ Al,
    int lda,
    const bf16* __restrict__ Wh, const bf16* __restrict__ Wm, const bf16* __restrict__ Wl,
    int ldw,
    const float* __restrict__ bias,
    bf16* __restrict__ Ch, bf16* __restrict__ Cm, bf16* __restrict__ Cl,
    float* __restrict__ Cf,
    int ldc, int N, int nchunks)
{
    extern __shared__ char smem[];
    const uint32_t sb = smem_u32(smem);
    const int tid  = threadIdx.x;
    const int wid  = tid >> 5;
    const int lane = tid & 31;
    const int g    = lane >> 2;
    const int tg   = lane & 3;
    const int wm   = wid & 1;        // 2 row-blocks of 64
    const int wn   = wid >> 1;       // 4 col-blocks of 16
    const int bm   = blockIdx.y * 128;
    const int bn   = blockIdx.x * 64;

    float accm[4][2][4], accs[4][2][4];
#pragma unroll
    for (int i = 0; i < 4; i++)
#pragma unroll
        for (int j = 0; j < 2; j++)
#pragma unroll
            for (int e = 0; e < 4; e++) { accm[i][j][e] = 0.0f; accs[i][j][e] = 0.0f; }

    // ---- stage loader: 3 A planes (128 rows) + 3 W planes (64 rows) ----
    auto load_stage = [&](int buf, int k0) {
        const uint32_t st = sb + buf * STAGE_B;
        const int row4 = tid >> 2;      // 0..63
        const int ch   = tid & 3;       // 4 x 16B = 64B = 32 bf16
#pragma unroll
        for (int h = 0; h < 2; ++h) {
            const int row = row4 + h * 64;
            const uint32_t d = st + row * ROWB + ch * 16;
            const size_t src = (size_t)(bm + row) * lda + k0 + ch * 8;
            CPA(d,              (const void*)(Ah + src), 16);
            CPA(d + A_PLANE,    (const void*)(Am + src), 16);
            CPA(d + 2*A_PLANE,  (const void*)(Al + src), 16);
        }
        {
            const int row = row4;
            const int n   = bn + row;
            const int pb  = (n < N) ? 16 : 0;
            const size_t src = (size_t)((n < N) ? n : 0) * ldw + k0 + ch * 8;
            const uint32_t d = st + W_OFF + row * ROWB + ch * 16;
            CPA(d,              (const void*)(Wh + src), pb);
            CPA(d + W_PLANE,    (const void*)(Wm + src), pb);
            CPA(d + 2*W_PLANE,  (const void*)(Wl + src), pb);
        }
        CPA_COMMIT();
    };

    const int nT = nchunks;             // chunks of 32 k
    load_stage(0, 0);
    if (nT > 1) load_stage(1, 32); else CPA_COMMIT();

    // ldmatrix per-thread addresses (verified layout, same as R6):
    // A: lanes 0-15 -> rows 0-15 (k-lo), lanes 16-31 -> rows 0-15 (k-hi)
    const uint32_t a_off = (uint32_t)((wm * 64 + (lane & 15)) * ROWB + (lane >> 4) * 16);
    // B: m0=(n0-7,klo) m1=(n0-7,khi) m2=(n8-15,klo) m3=(n8-15,khi)
    const int b_row = ((lane >> 4) & 1) * 8 + (lane & 7);
    const int b_ch  = (lane >> 3) & 1;
    const uint32_t b_off = (uint32_t)(W_OFF + (wn * 16 + b_row) * ROWB + b_ch * 16);

    for (int t = 0; t < nT; ++t) {
        if (t + 2 < nT) load_stage((t + 2) % NSTG, (t + 2) * 32);
        else            CPA_COMMIT();
        CPA_WAIT2();
        __syncthreads();

        const uint32_t st = sb + (t % NSTG) * STAGE_B;
#pragma unroll
        for (int ks = 0; ks < 2; ++ks) {
            const uint32_t ko = ks * 32;    // 16 bf16
            uint32_t ah[4][4], am[4][4], al[4][4];
            uint32_t bh[2][2], bm_[2][2], bl[2][2];
            const uint32_t ab = st + a_off + ko;
#pragma unroll
            for (int mt = 0; mt < 4; ++mt) {
                const uint32_t r = ab + mt * (16 * ROWB);
                LDSM4(ah[mt][0], ah[mt][1], ah[mt][2], ah[mt][3], r);
                LDSM4(am[mt][0], am[mt][1], am[mt][2], am[mt][3], r + A_PLANE);
                LDSM4(al[mt][0], al[mt][1], al[mt][2], al[mt][3], r + 2*A_PLANE);
            }
            const uint32_t bb = st + b_off + ko;
            LDSM4(bh[0][0],  bh[0][1],  bh[1][0],  bh[1][1],  bb);
            LDSM4(bm_[0][0], bm_[0][1], bm_[1][0], bm_[1][1], bb + W_PLANE);
            LDSM4(bl[0][0],  bl[0][1],  bl[1][0],  bl[1][1],  bb + 2*W_PLANE);
#pragma unroll
            for (int mt = 0; mt < 4; ++mt)
#pragma unroll
                for (int nt = 0; nt < 2; ++nt) {
                    MMAB(accm[mt][nt], ah[mt], bh[nt]);     // h*h  -> main
                    MMAB(accs[mt][nt], ah[mt], bm_[nt]);    // h*m  -> small
                    MMAB(accs[mt][nt], am[mt], bh[nt]);     // m*h
                    MMAB(accs[mt][nt], ah[mt], bl[nt]);     // h*l
                    MMAB(accs[mt][nt], al[mt], bh[nt]);     // l*h
                    MMAB(accs[mt][nt], am[mt], bm_[nt]);    // m*m
                }
        }
        __syncthreads();
    }

    // ---- epilogue: final = main + small ----
#pragma unroll
    for (int nt = 0; nt < 2; ++nt) {
        const int cg = bn + wn * 16 + nt * 8 + tg * 2;
#pragma unroll
        for (int mt = 0; mt < 4; ++mt) {
            const int r0 = bm + wm * 64 + mt * 16 + g;
#pragma unroll
            for (int h = 0; h < 2; ++h) {
                const int r = r0 + h * 8;
                float v0 = (accm[mt][nt][2*h+0] + accs[mt][nt][2*h+0]);
                float v1 = (accm[mt][nt][2*h+1] + accs[mt][nt][2*h+1]);
                if (OUTMODE == 0) {
                    v0 = fmaxf(v0 + bias[cg],     0.0f);
                    v1 = fmaxf(v1 + bias[cg + 1], 0.0f);
                    bf16 h0, m0, l0, h1, m1, l1;
                    bf16_split3(v0, h0, m0, l0);
                    bf16_split3(v1, h1, m1, l1);
                    const size_t gdx = (size_t)r * ldc + cg;
                    __nv_bfloat162 p;
                    p.x = h0; p.y = h1; *(uint32_t*)(Ch + gdx) = *(uint32_t*)&p;
                    p.x = m0; p.y = m1; *(uint32_t*)(Cm + gdx) = *(uint32_t*)&p;
                    p.x = l0; p.y = l1; *(uint32_t*)(Cl + gdx) = *(uint32_t*)&p;
                } else {
                    if (cg < N)     Cf[(size_t)r * ldc + cg]     = tanhf(v0 + bias[cg]);
                    if (cg + 1 < N) Cf[(size_t)r * ldc + cg + 1] = tanhf(v1 + bias[cg + 1]);
                }
            }
        }
    }
}

// ---------------- pre-split kernels ----------------
// seq[:,0:2560]+[2564:3076] -> packed [M,3072] 3 planes
__global__ void split_seq3_kernel(const float* __restrict__ seq,
                                  bf16* __restrict__ ph, bf16* __restrict__ pm,
                                  bf16* __restrict__ pl)
{
    const long long t = (long long)blockIdx.x * blockDim.x + threadIdx.x;
    const long long total = (long long)MROWS * SEQC / 8;
    if (t >= total) return;
    const long long e = t * 8;
    const int mr = (int)(e / SEQC);
    const int c0 = (int)(e % SEQC);
    const int src = (c0 < 2560) ? c0 : c0 + 4;
    const float4 v0 = *(const float4*)(seq + (size_t)mr * 3076 + src);
    const float4 v1 = *(const float4*)(seq + (size_t)mr * 3076 + src + 4);
    const float v[8] = {v0.x, v0.y, v0.z, v0.w, v1.x, v1.y, v1.z, v1.w};
    bf16 h[8], m[8], l[8];
#pragma unroll
    for (int i = 0; i < 8; i++) bf16_split3(v[i], h[i], m[i], l[i]);
    const size_t d = (size_t)mr * SEQC + c0;
    *(uint4*)(ph + d) = *(uint4*)h;
    *(uint4*)(pm + d) = *(uint4*)m;
    *(uint4*)(pl + d) = *(uint4*)l;
}

__global__ void split_w3_kernel(const float* __restrict__ W, int N, int K, int Kp,
                                bf16* __restrict__ ph, bf16* __restrict__ pm,
                                bf16* __restrict__ pl)
{
    const int i = blockIdx.x * blockDim.x + threadIdx.x;
    if (i >= N * Kp) return;
    const int n = i / Kp, k = i % Kp;
    const float v = (k < K) ? W[(size_t)n * K + k] : 0.0f;
    bf16 h, m, l;
    bf16_split3(v, h, m, l);
    ph[i] = h; pm[i] = m; pl[i] = l;
}

// cc cols [256,260) = relu(pos); [388,448) = 0  (3 planes)
__global__ void pos_pad3_kernel(const float* __restrict__ seq,
                                bf16* __restrict__ ph, bf16* __restrict__ pm,
                                bf16* __restrict__ pl)
{
    const int i = blockIdx.x * blockDim.x + threadIdx.x;
    if (i >= MROWS * 64) return;
    const int mr = i >> 6, j = i & 63;
    float v = 0.0f;
    int col;
    if (j < 4) { v = fmaxf(seq[(size_t)mr * 3076 + 2560 + j], 0.0f); col = 256 + j; }
    else       { col = 384 + j; }
    bf16 h, m, l;
    bf16_split3(v, h, m, l);
    const size_t d = (size_t)mr * 448 + col;
    ph[d] = h; pm[d] = m; pl[d] = l;
}

// ---------------- Sinkhorn ----------------
__global__ __launch_bounds__(512) void sinkhorn_kernel(
    const float* __restrict__ logits, float* __restrict__ out)
{
    __shared__ float X[36][37];
    __shared__ float red[36];
    const int b = blockIdx.x;
    const int t = threadIdx.x;
    const float* src = logits + (size_t)b * 1296;

    for (int i = t; i < 1296; i += 512)
        X[i / 36][i % 36] = expf(src[i] * TAU_INV);
    __syncthreads();

    for (int it = 0; it < 20; ++it) {
        if (t < 36) {
            float mx = -INFINITY;
#pragma unroll
            for (int c = 0; c < 36; c++) mx = fmaxf(mx, X[t][c]);
            float s = 0.0f;
#pragma unroll
            for (int c = 0; c < 36; c++) s += expf(X[t][c] - mx);
            red[t] = mx + logf(s);
        }
        __syncthreads();
        for (int i = t; i < 1296; i += 512) X[i / 36][i % 36] -= red[i / 36];
        __syncthreads();
        if (t < 36) {
            float mx = -INFINITY;
#pragma unroll
            for (int r = 0; r < 36; r++) mx = fmaxf(mx, X[r][t]);
            float s = 0.0f;
#pragma unroll
            for (int r = 0; r < 36; r++) s += expf(X[r][t] - mx);
            red[t] = mx + logf(s);
        }
        __syncthreads();
        for (int i = t; i < 1296; i += 512) X[i / 36][i % 36] -= red[i % 36];
        __syncthreads();
    }
    for (int i = t; i < 1296; i += 512)
        out[(size_t)b * 1296 + i] = expf(X[i / 36][i % 36]);
}

// ---------------- host ----------------
extern "C" void kernel_launch(void* const* d_in, const int* in_sizes, int n_in,
                              void* d_out, int out_size)
{
    const float* seq   = (const float*)d_in[0];
    const float* W1t_w = (const float*)d_in[1];
    const float* W1t_b = (const float*)d_in[2];
    const float* W1v_w = (const float*)d_in[3];
    const float* W1v_b = (const float*)d_in[4];
    const float* W2v_w = (const float*)d_in[5];
    const float* W2v_b = (const float*)d_in[6];
    const float* W1s_w = (const float*)d_in[7];
    const float* W1s_b = (const float*)d_in[8];
    const float* Wfp_w = (const float*)d_in[9];
    const float* Wfp_b = (const float*)d_in[10];
    const float* Wfc_w = (const float*)d_in[11];
    const float* Wfc_b = (const float*)d_in[12];
    float* out = (float*)d_out;

    bf16 *sq[3], *xv[3], *cc[3], *a3[3], *wp[3];
    float* logits;
    {
        bf16* p;
        cudaGetSymbolAddress((void**)&p, g_seqP);
        sq[0] = p; sq[1] = p + (size_t)MROWS * SEQC; sq[2] = p + 2 * (size_t)MROWS * SEQC;
        cudaGetSymbolAddress((void**)&p, g_xvP);
        xv[0] = p; xv[1] = p + (size_t)MROWS * 512; xv[2] = p + 2 * (size_t)MROWS * 512;
        cudaGetSymbolAddress((void**)&p, g_ccP);
        cc[0] = p; cc[1] = p + (size_t)MROWS * 448; cc[2] = p + 2 * (size_t)MROWS * 448;
        cudaGetSymbolAddress((void**)&p, g_a3P);
        a3[0] = p; a3[1] = p + (size_t)MROWS * 256; a3[2] = p + 2 * (size_t)MROWS * 256;
        cudaGetSymbolAddress((void**)&p, g_wP);
        const size_t wsz = 128*512 + 512*2048 + 128*512 + 128*512 + 256*448 + 36*256;
        wp[0] = p; wp[1] = p + wsz; wp[2] = p + 2 * wsz;
        cudaGetSymbolAddress((void**)&logits, g_logits);
    }

    cudaFuncSetAttribute(gemm_bf6<0>, cudaFuncAttributeMaxDynamicSharedMemorySize, GEMM_SMEM);
    cudaFuncSetAttribute(gemm_bf6<1>, cudaFuncAttributeMaxDynamicSharedMemorySize, GEMM_SMEM);

    // ---- splits ----
    {
        const long long n = (long long)MROWS * SEQC / 8;
        split_seq3_kernel<<<(unsigned)((n + 255) / 256), 256>>>(seq, sq[0], sq[1], sq[2]);
    }
    split_w3_kernel<<<(128*512  + 255) / 256, 256>>>(W1t_w, 128, 512, 512,
        wp[0] + WOFF_TXT,  wp[1] + WOFF_TXT,  wp[2] + WOFF_TXT);
    split_w3_kernel<<<(512*2048 + 255) / 256, 256>>>(W1v_w, 512, 2048, 2048,
        wp[0] + WOFF_VIS1, wp[1] + WOFF_VIS1, wp[2] + WOFF_VIS1);
    split_w3_kernel<<<(128*512  + 255) / 256, 256>>>(W2v_w, 128, 512, 512,
        wp[0] + WOFF_VIS2, wp[1] + WOFF_VIS2, wp[2] + WOFF_VIS2);
    split_w3_kernel<<<(128*512  + 255) / 256, 256>>>(W1s_w, 128, 512, 512,
        wp[0] + WOFF_SEN,  wp[1] + WOFF_SEN,  wp[2] + WOFF_SEN);
    split_w3_kernel<<<(256*448  + 255) / 256, 256>>>(Wfp_w, 256, 388, 448,
        wp[0] + WOFF_FCP,  wp[1] + WOFF_FCP,  wp[2] + WOFF_FCP);
    split_w3_kernel<<<(36*256   + 255) / 256, 256>>>(Wfc_w, 36, 256, 256,
        wp[0] + WOFF_FC,   wp[1] + WOFF_FC,   wp[2] + WOFF_FC);
    pos_pad3_kernel<<<(MROWS * 64 + 255) / 256, 256>>>(seq, cc[0], cc[1], cc[2]);

    const int mT = MROWS / 128;   // 144

    // vis1: K=2048 -> xv [M,512]
    gemm_bf6<0><<<dim3(8, mT), 256, GEMM_SMEM>>>(
        sq[0] + 512, sq[1] + 512, sq[2] + 512, SEQC,
        wp[0] + WOFF_VIS1, wp[1] + WOFF_VIS1, wp[2] + WOFF_VIS1, 2048, W1v_b,
        xv[0], xv[1], xv[2], nullptr, 512, 512, 64);
    // txt: K=512 -> cc cols [0,128)
    gemm_bf6<0><<<dim3(2, mT), 256, GEMM_SMEM>>>(
        sq[0], sq[1], sq[2], SEQC,
        wp[0] + WOFF_TXT, wp[1] + WOFF_TXT, wp[2] + WOFF_TXT, 512, W1t_b,
        cc[0], cc[1], cc[2], nullptr, 448, 128, 16);
    // sen: K=512 -> cc cols [260,388)
    gemm_bf6<0><<<dim3(2, mT), 256, GEMM_SMEM>>>(
        sq[0] + 2560, sq[1] + 2560, sq[2] + 2560, SEQC,
        wp[0] + WOFF_SEN, wp[1] + WOFF_SEN, wp[2] + WOFF_SEN, 512, W1s_b,
        cc[0] + 260, cc[1] + 260, cc[2] + 260, nullptr, 448, 128, 16);
    // vis2: K=512 -> cc cols [128,256)
    gemm_bf6<0><<<dim3(2, mT), 256, GEMM_SMEM>>>(
        xv[0], xv[1], xv[2], 512,
        wp[0] + WOFF_VIS2, wp[1] + WOFF_VIS2, wp[2] + WOFF_VIS2, 512, W2v_b,
        cc[0] + 128, cc[1] + 128, cc[2] + 128, nullptr, 448, 128, 16);
    // fc_pos: K=448 -> a3 [M,256]
    gemm_bf6<0><<<dim3(4, mT), 256, GEMM_SMEM>>>(
        cc[0], cc[1], cc[2], 448,
        wp[0] + WOFF_FCP, wp[1] + WOFF_FCP, wp[2] + WOFF_FCP, 448, Wfp_b,
        a3[0], a3[1], a3[2], nullptr, 256, 256, 14);
    // fc: K=256 -> logits [M,36], tanh
    gemm_bf6<1><<<dim3(1, mT), 256, GEMM_SMEM>>>(
        a3[0], a3[1], a3[2], 256,
        wp[0] + WOFF_FC, wp[1] + WOFF_FC, wp[2] + WOFF_FC, 256, Wfc_b,
        nullptr, nullptr, nullptr, logits, 36, 36, 8);

    sinkhorn_kernel<<<512, 512>>>(logits, out);
}

// round 11
// speedup vs baseline: 2.7503x; 1.5757x over previous
#include <cuda_runtime.h>
#include <cuda_fp16.h>
#include <math.h>
#include <stdint.h>

#define MROWS 18432
#define TAU_INV 20.0f
#define MSCALE 4096.0f
#define INV_MSCALE (1.0f / 4096.0f)

typedef __half f16;

// ---------------- scratch (device globals; alloc-free) ----------------
// 2 fp16 planes (h, m) per tensor: v == h + m/4096 + O(2^-24 v)
#define SEQC 3072
__device__ __align__(128) f16 g_seqP[2][(size_t)MROWS * SEQC];
__device__ __align__(128) f16 g_xvP [2][(size_t)MROWS * 512];
__device__ __align__(128) f16 g_ccP [2][(size_t)MROWS * 448];
__device__ __align__(128) f16 g_a3P [2][(size_t)MROWS * 256];
__device__ __align__(128) f16 g_wP  [2][128*512 + 512*2048 + 128*512 + 128*512 + 256*448 + 36*256];
__device__ __align__(128) float g_logits[(size_t)MROWS * 36];

#define WOFF_TXT   0
#define WOFF_VIS1  (WOFF_TXT  + 128*512)
#define WOFF_VIS2  (WOFF_VIS1 + 512*2048)
#define WOFF_SEN   (WOFF_VIS2 + 128*512)
#define WOFF_FCP   (WOFF_SEN  + 128*512)
#define WOFF_FC    (WOFF_FCP  + 256*448)

// ---------------- smem layout ----------------
// row: 32 data f16 (64B) + 8 pad = 80B, conflict-free ldmatrix.
#define ROWB    80
#define A_PLANE (128 * ROWB)           // 10240
#define W_PLANE (64 * ROWB)            // 5120
#define W_OFF   (2 * A_PLANE)          // 20480
#define STAGE_B (2 * A_PLANE + 2 * W_PLANE)   // 30720
#define NSTG    3
#define GEMM_SMEM (NSTG * STAGE_B)     // 92160

// ---------------- PTX helpers ----------------
__device__ __forceinline__ uint32_t smem_u32(const void* p) {
    uint32_t a;
    asm("{ .reg .u64 t; cvta.to.shared.u64 t, %1; cvt.u32.u64 %0, t; }" : "=r"(a) : "l"(p));
    return a;
}

#define CPA(dst, src, pb) \
    asm volatile("cp.async.cg.shared.global [%0], [%1], 16, %2;" \
                 :: "r"(dst), "l"(src), "r"(pb) : "memory")
#define CPA_COMMIT() asm volatile("cp.async.commit_group;" ::: "memory")
#define CPA_WAIT2()  asm volatile("cp.async.wait_group 2;" ::: "memory")

#define LDSM4(r0, r1, r2, r3, a) \
    asm volatile("ldmatrix.sync.aligned.m8n8.x4.shared.b16 {%0,%1,%2,%3}, [%4];" \
                 : "=r"(r0), "=r"(r1), "=r"(r2), "=r"(r3) : "r"(a))

#define MMAH(d, a, b) \
    asm volatile("mma.sync.aligned.m16n8k16.row.col.f32.f16.f16.f32 " \
                 "{%0,%1,%2,%3}, {%4,%5,%6,%7}, {%8,%9}, {%0,%1,%2,%3};" \
                 : "+f"((d)[0]), "+f"((d)[1]), "+f"((d)[2]), "+f"((d)[3]) \
                 : "r"((a)[0]), "r"((a)[1]), "r"((a)[2]), "r"((a)[3]), \
                   "r"((b)[0]), "r"((b)[1]))

// 2-way scaled fp16 split: v == h + m/4096 + O(2^-24 v)
__device__ __forceinline__ void f16_split2(float v, f16& h, f16& m) {
    h = __float2half_rn(v);
    m = __float2half_rn((v - __half2float(h)) * MSCALE);
}

// ---------------- GEMM: C[M,N] = act(A[M,K] @ W[N,K]^T + bias) ----------------
// A, W given as 2 fp16 planes (h, m/4096). 3-term emulation, dual accumulators:
//   acc_main = sum h*h' ;  acc_s = sum(h*m' + m*h') ;  final = main + s/4096
// CTA tile 128x64, 8 warps (2x4), warp tile 64x16. M tile-exact.
// OUTMODE 0: relu -> 2 f16 planes. OUTMODE 1: tanh -> fp32 (col guard).
template <int OUTMODE>
__global__ __launch_bounds__(256, 1) void gemm_f16e(
    const f16* __restrict__ Ah, const f16* __restrict__ Am, int lda,
    const f16* __restrict__ Wh, const f16* __restrict__ Wm, int ldw,
    const float* __restrict__ bias,
    f16* __restrict__ Ch, f16* __restrict__ Cm, float* __restrict__ Cf,
    int ldc, int N, int nchunks)
{
    extern __shared__ char smem[];
    const uint32_t sb = smem_u32(smem);
    const int tid  = threadIdx.x;
    const int wid  = tid >> 5;
    const int lane = tid & 31;
    const int g    = lane >> 2;
    const int tg   = lane & 3;
    const int wm   = wid & 1;        // 2 row-blocks of 64
    const int wn   = wid >> 1;       // 4 col-blocks of 16
    const int bm   = blockIdx.y * 128;
    const int bn   = blockIdx.x * 64;

    float accm[4][2][4], accs[4][2][4];
#pragma unroll
    for (int i = 0; i < 4; i++)
#pragma unroll
        for (int j = 0; j < 2; j++)
#pragma unroll
            for (int e = 0; e < 4; e++) { accm[i][j][e] = 0.0f; accs[i][j][e] = 0.0f; }

    // ---- stage loader: 2 A planes (128 rows) + 2 W planes (64 rows) ----
    auto load_stage = [&](int buf, int k0) {
        const uint32_t st = sb + buf * STAGE_B;
        const int row4 = tid >> 2;      // 0..63
        const int ch   = tid & 3;       // 4 x 16B = 64B = 32 f16
#pragma unroll
        for (int h = 0; h < 2; ++h) {
            const int row = row4 + h * 64;
            const uint32_t d = st + row * ROWB + ch * 16;
            const size_t src = (size_t)(bm + row) * lda + k0 + ch * 8;
            CPA(d,           (const void*)(Ah + src), 16);
            CPA(d + A_PLANE, (const void*)(Am + src), 16);
        }
        {
            const int row = row4;
            const int n   = bn + row;
            const int pb  = (n < N) ? 16 : 0;
            const size_t src = (size_t)((n < N) ? n : 0) * ldw + k0 + ch * 8;
            const uint32_t d = st + W_OFF + row * ROWB + ch * 16;
            CPA(d,           (const void*)(Wh + src), pb);
            CPA(d + W_PLANE, (const void*)(Wm + src), pb);
        }
        CPA_COMMIT();
    };

    const int nT = nchunks;             // chunks of 32 k
    load_stage(0, 0);
    if (nT > 1) load_stage(1, 32); else CPA_COMMIT();

    // ldmatrix per-thread addresses (layout verified in R10):
    const uint32_t a_off = (uint32_t)((wm * 64 + (lane & 15)) * ROWB + (lane >> 4) * 16);
    const int b_row = ((lane >> 4) & 1) * 8 + (lane & 7);
    const int b_ch  = (lane >> 3) & 1;
    const uint32_t b_off = (uint32_t)(W_OFF + (wn * 16 + b_row) * ROWB + b_ch * 16);

    for (int t = 0; t < nT; ++t) {
        if (t + 2 < nT) load_stage((t + 2) % NSTG, (t + 2) * 32);
        else            CPA_COMMIT();
        CPA_WAIT2();
        __syncthreads();

        const uint32_t st = sb + (t % NSTG) * STAGE_B;
#pragma unroll
        for (int ks = 0; ks < 2; ++ks) {
            const uint32_t ko = ks * 32;    // 16 f16
            uint32_t ah[4][4], am[4][4];
            uint32_t bh[2][2], bm_[2][2];
            const uint32_t ab = st + a_off + ko;
#pragma unroll
            for (int mt = 0; mt < 4; ++mt) {
                const uint32_t r = ab + mt * (16 * ROWB);
                LDSM4(ah[mt][0], ah[mt][1], ah[mt][2], ah[mt][3], r);
                LDSM4(am[mt][0], am[mt][1], am[mt][2], am[mt][3], r + A_PLANE);
            }
            const uint32_t bb = st + b_off + ko;
            LDSM4(bh[0][0],  bh[0][1],  bh[1][0],  bh[1][1],  bb);
            LDSM4(bm_[0][0], bm_[0][1], bm_[1][0], bm_[1][1], bb + W_PLANE);
#pragma unroll
            for (int mt = 0; mt < 4; ++mt)
#pragma unroll
                for (int nt = 0; nt < 2; ++nt) {
                    MMAH(accm[mt][nt], ah[mt], bh[nt]);     // h*h  -> main
                    MMAH(accs[mt][nt], ah[mt], bm_[nt]);    // h*m  -> scaled
                    MMAH(accs[mt][nt], am[mt], bh[nt]);     // m*h  -> scaled
                }
        }
        __syncthreads();
    }

    // ---- epilogue: final = main + s/4096 ----
#pragma unroll
    for (int nt = 0; nt < 2; ++nt) {
        const int cg = bn + wn * 16 + nt * 8 + tg * 2;
#pragma unroll
        for (int mt = 0; mt < 4; ++mt) {
            const int r0 = bm + wm * 64 + mt * 16 + g;
#pragma unroll
            for (int h = 0; h < 2; ++h) {
                const int r = r0 + h * 8;
                float v0 = fmaf(accs[mt][nt][2*h+0], INV_MSCALE, accm[mt][nt][2*h+0]);
                float v1 = fmaf(accs[mt][nt][2*h+1], INV_MSCALE, accm[mt][nt][2*h+1]);
                if (OUTMODE == 0) {
                    v0 = fmaxf(v0 + bias[cg],     0.0f);
                    v1 = fmaxf(v1 + bias[cg + 1], 0.0f);
                    f16 h0, m0, h1, m1;
                    f16_split2(v0, h0, m0);
                    f16_split2(v1, h1, m1);
                    const size_t gdx = (size_t)r * ldc + cg;
                    __half2 p;
                    p.x = h0; p.y = h1; *(uint32_t*)(Ch + gdx) = *(uint32_t*)&p;
                    p.x = m0; p.y = m1; *(uint32_t*)(Cm + gdx) = *(uint32_t*)&p;
                } else {
                    if (cg < N)     Cf[(size_t)r * ldc + cg]     = tanhf(v0 + bias[cg]);
                    if (cg + 1 < N) Cf[(size_t)r * ldc + cg + 1] = tanhf(v1 + bias[cg + 1]);
                }
            }
        }
    }
}

// ---------------- pre-split kernels ----------------
// seq[:,0:2560]+[2564:3076] -> packed [M,3072] 2 planes
__global__ void split_seq2_kernel(const float* __restrict__ seq,
                                  f16* __restrict__ ph, f16* __restrict__ pm)
{
    const long long t = (long long)blockIdx.x * blockDim.x + threadIdx.x;
    const long long total = (long long)MROWS * SEQC / 8;
    if (t >= total) return;
    const long long e = t * 8;
    const int mr = (int)(e / SEQC);
    const int c0 = (int)(e % SEQC);
    const int src = (c0 < 2560) ? c0 : c0 + 4;
    const float4 v0 = *(const float4*)(seq + (size_t)mr * 3076 + src);
    const float4 v1 = *(const float4*)(seq + (size_t)mr * 3076 + src + 4);
    const float v[8] = {v0.x, v0.y, v0.z, v0.w, v1.x, v1.y, v1.z, v1.w};
    f16 h[8], m[8];
#pragma unroll
    for (int i = 0; i < 8; i++) f16_split2(v[i], h[i], m[i]);
    const size_t d = (size_t)mr * SEQC + c0;
    *(uint4*)(ph + d) = *(uint4*)h;
    *(uint4*)(pm + d) = *(uint4*)m;
}

__global__ void split_w2_kernel(const float* __restrict__ W, int N, int K, int Kp,
                                f16* __restrict__ ph, f16* __restrict__ pm)
{
    const int i = blockIdx.x * blockDim.x + threadIdx.x;
    if (i >= N * Kp) return;
    const int n = i / Kp, k = i % Kp;
    const float v = (k < K) ? W[(size_t)n * K + k] : 0.0f;
    f16 h, m;
    f16_split2(v, h, m);
    ph[i] = h; pm[i] = m;
}

// cc cols [256,260) = relu(pos); [388,448) = 0  (2 planes)
__global__ void pos_pad2_kernel(const float* __restrict__ seq,
                                f16* __restrict__ ph, f16* __restrict__ pm)
{
    const int i = blockIdx.x * blockDim.x + threadIdx.x;
    if (i >= MROWS * 64) return;
    const int mr = i >> 6, j = i & 63;
    float v = 0.0f;
    int col;
    if (j < 4) { v = fmaxf(seq[(size_t)mr * 3076 + 2560 + j], 0.0f); col = 256 + j; }
    else       { col = 384 + j; }
    f16 h, m;
    f16_split2(v, h, m);
    const size_t d = (size_t)mr * 448 + col;
    ph[d] = h; pm[d] = m;
}

// ---------------- Sinkhorn ----------------
__global__ __launch_bounds__(512) void sinkhorn_kernel(
    const float* __restrict__ logits, float* __restrict__ out)
{
    __shared__ float X[36][37];
    __shared__ float red[36];
    const int b = blockIdx.x;
    const int t = threadIdx.x;
    const float* src = logits + (size_t)b * 1296;

    for (int i = t; i < 1296; i += 512)
        X[i / 36][i % 36] = expf(src[i] * TAU_INV);
    __syncthreads();

    for (int it = 0; it < 20; ++it) {
        if (t < 36) {
            float mx = -INFINITY;
#pragma unroll
            for (int c = 0; c < 36; c++) mx = fmaxf(mx, X[t][c]);
            float s = 0.0f;
#pragma unroll
            for (int c = 0; c < 36; c++) s += expf(X[t][c] - mx);
            red[t] = mx + logf(s);
        }
        __syncthreads();
        for (int i = t; i < 1296; i += 512) X[i / 36][i % 36] -= red[i / 36];
        __syncthreads();
        if (t < 36) {
            float mx = -INFINITY;
#pragma unroll
            for (int r = 0; r < 36; r++) mx = fmaxf(mx, X[r][t]);
            float s = 0.0f;
#pragma unroll
            for (int r = 0; r < 36; r++) s += expf(X[r][t] - mx);
            red[t] = mx + logf(s);
        }
        __syncthreads();
        for (int i = t; i < 1296; i += 512) X[i / 36][i % 36] -= red[i % 36];
        __syncthreads();
    }
    for (int i = t; i < 1296; i += 512)
        out[(size_t)b * 1296 + i] = expf(X[i / 36][i % 36]);
}

// ---------------- host ----------------
extern "C" void kernel_launch(void* const* d_in, const int* in_sizes, int n_in,
                              void* d_out, int out_size)
{
    const float* seq   = (const float*)d_in[0];
    const float* W1t_w = (const float*)d_in[1];
    const float* W1t_b = (const float*)d_in[2];
    const float* W1v_w = (const float*)d_in[3];
    const float* W1v_b = (const float*)d_in[4];
    const float* W2v_w = (const float*)d_in[5];
    const float* W2v_b = (const float*)d_in[6];
    const float* W1s_w = (const float*)d_in[7];
    const float* W1s_b = (const float*)d_in[8];
    const float* Wfp_w = (const float*)d_in[9];
    const float* Wfp_b = (const float*)d_in[10];
    const float* Wfc_w = (const float*)d_in[11];
    const float* Wfc_b = (const float*)d_in[12];
    float* out = (float*)d_out;

    f16 *sq[2], *xv[2], *cc[2], *a3[2], *wp[2];
    float* logits;
    {
        f16* p;
        cudaGetSymbolAddress((void**)&p, g_seqP);
        sq[0] = p; sq[1] = p + (size_t)MROWS * SEQC;
        cudaGetSymbolAddress((void**)&p, g_xvP);
        xv[0] = p; xv[1] = p + (size_t)MROWS * 512;
        cudaGetSymbolAddress((void**)&p, g_ccP);
        cc[0] = p; cc[1] = p + (size_t)MROWS * 448;
        cudaGetSymbolAddress((void**)&p, g_a3P);
        a3[0] = p; a3[1] = p + (size_t)MROWS * 256;
        cudaGetSymbolAddress((void**)&p, g_wP);
        const size_t wsz = 128*512 + 512*2048 + 128*512 + 128*512 + 256*448 + 36*256;
        wp[0] = p; wp[1] = p + wsz;
        cudaGetSymbolAddress((void**)&logits, g_logits);
    }

    cudaFuncSetAttribute(gemm_f16e<0>, cudaFuncAttributeMaxDynamicSharedMemorySize, GEMM_SMEM);
    cudaFuncSetAttribute(gemm_f16e<1>, cudaFuncAttributeMaxDynamicSharedMemorySize, GEMM_SMEM);

    // ---- splits ----
    {
        const long long n = (long long)MROWS * SEQC / 8;
        split_seq2_kernel<<<(unsigned)((n + 255) / 256), 256>>>(seq, sq[0], sq[1]);
    }
    split_w2_kernel<<<(128*512  + 255) / 256, 256>>>(W1t_w, 128, 512, 512,
        wp[0] + WOFF_TXT,  wp[1] + WOFF_TXT);
    split_w2_kernel<<<(512*2048 + 255) / 256, 256>>>(W1v_w, 512, 2048, 2048,
        wp[0] + WOFF_VIS1, wp[1] + WOFF_VIS1);
    split_w2_kernel<<<(128*512  + 255) / 256, 256>>>(W2v_w, 128, 512, 512,
        wp[0] + WOFF_VIS2, wp[1] + WOFF_VIS2);
    split_w2_kernel<<<(128*512  + 255) / 256, 256>>>(W1s_w, 128, 512, 512,
        wp[0] + WOFF_SEN,  wp[1] + WOFF_SEN);
    split_w2_kernel<<<(256*448  + 255) / 256, 256>>>(Wfp_w, 256, 388, 448,
        wp[0] + WOFF_FCP,  wp[1] + WOFF_FCP);
    split_w2_kernel<<<(36*256   + 255) / 256, 256>>>(Wfc_w, 36, 256, 256,
        wp[0] + WOFF_FC,   wp[1] + WOFF_FC);
    pos_pad2_kernel<<<(MROWS * 64 + 255) / 256, 256>>>(seq, cc[0], cc[1]);

    const int mT = MROWS / 128;   // 144

    // vis1: K=2048 -> xv [M,512]
    gemm_f16e<0><<<dim3(8, mT), 256, GEMM_SMEM>>>(
        sq[0] + 512, sq[1] + 512, SEQC,
        wp[0] + WOFF_VIS1, wp[1] + WOFF_VIS1, 2048, W1v_b,
        xv[0], xv[1], nullptr, 512, 512, 64);
    // txt: K=512 -> cc cols [0,128)
    gemm_f16e<0><<<dim3(2, mT), 256, GEMM_SMEM>>>(
        sq[0], sq[1], SEQC,
        wp[0] + WOFF_TXT, wp[1] + WOFF_TXT, 512, W1t_b,
        cc[0], cc[1], nullptr, 448, 128, 16);
    // sen: K=512 -> cc cols [260,388)
    gemm_f16e<0><<<dim3(2, mT), 256, GEMM_SMEM>>>(
        sq[0] + 2560, sq[1] + 2560, SEQC,
        wp[0] + WOFF_SEN, wp[1] + WOFF_SEN, 512, W1s_b,
        cc[0] + 260, cc[1] + 260, nullptr, 448, 128, 16);
    // vis2: K=512 -> cc cols [128,256)
    gemm_f16e<0><<<dim3(2, mT), 256, GEMM_SMEM>>>(
        xv[0], xv[1], 512,
        wp[0] + WOFF_VIS2, wp[1] + WOFF_VIS2, 512, W2v_b,
        cc[0] + 128, cc[1] + 128, nullptr, 448, 128, 16);
    // fc_pos: K=448 -> a3 [M,256]
    gemm_f16e<0><<<dim3(4, mT), 256, GEMM_SMEM>>>(
        cc[0], cc[1], 448,
        wp[0] + WOFF_FCP, wp[1] + WOFF_FCP, 448, Wfp_b,
        a3[0], a3[1], nullptr, 256, 256, 14);
    // fc: K=256 -> logits [M,36], tanh
    gemm_f16e<1><<<dim3(1, mT), 256, GEMM_SMEM>>>(
        a3[0], a3[1], 256,
        wp[0] + WOFF_FC, wp[1] + WOFF_FC, 256, Wfc_b,
        nullptr, nullptr, logits, 36, 36, 8);

    sinkhorn_kernel<<<512, 512>>>(logits, out);
}

// round 12
// speedup vs baseline: 3.1832x; 1.1574x over previous
#include <cuda_runtime.h>
#include <cuda_fp16.h>
#include <math.h>
#include <stdint.h>

#define MROWS 18432
#define TAU_INV 20.0f
#define MSCALE 4096.0f
#define INV_MSCALE (1.0f / 4096.0f)

typedef __half f16;

// ---------------- scratch (device globals; alloc-free) ----------------
// 2 fp16 planes (h, m) per tensor: v == h + m/4096 + O(2^-24 v)
#define SEQC 3072
__device__ __align__(128) f16 g_seqP[2][(size_t)MROWS * SEQC];
__device__ __align__(128) f16 g_xvP [2][(size_t)MROWS * 512];
__device__ __align__(128) f16 g_ccP [2][(size_t)MROWS * 448];
__device__ __align__(128) f16 g_a3P [2][(size_t)MROWS * 256];
__device__ __align__(128) f16 g_wP  [2][128*512 + 512*2048 + 128*512 + 128*512 + 256*448 + 36*256];
__device__ __align__(128) float g_logits[(size_t)MROWS * 36];

#define WOFF_TXT   0
#define WOFF_VIS1  (WOFF_TXT  + 128*512)
#define WOFF_VIS2  (WOFF_VIS1 + 512*2048)
#define WOFF_SEN   (WOFF_VIS2 + 128*512)
#define WOFF_FCP   (WOFF_SEN  + 128*512)
#define WOFF_FC    (WOFF_FCP  + 256*448)

// ---------------- smem layout ----------------
// row: 32 data f16 (64B) + 8 pad = 80B, conflict-free ldmatrix.
#define ROWB    80
#define A_PLANE (128 * ROWB)           // 10240
#define W_PLANE (128 * ROWB)           // 10240 (N-tile now 128)
#define W_OFF   (2 * A_PLANE)          // 20480
#define STAGE_B (2 * A_PLANE + 2 * W_PLANE)   // 40960
#define NSTG    3
#define GEMM_SMEM (NSTG * STAGE_B)     // 122880

// ---------------- PTX helpers ----------------
__device__ __forceinline__ uint32_t smem_u32(const void* p) {
    uint32_t a;
    asm("{ .reg .u64 t; cvta.to.shared.u64 t, %1; cvt.u32.u64 %0, t; }" : "=r"(a) : "l"(p));
    return a;
}

#define CPA(dst, src, pb) \
    asm volatile("cp.async.cg.shared.global [%0], [%1], 16, %2;" \
                 :: "r"(dst), "l"(src), "r"(pb) : "memory")
#define CPA_COMMIT() asm volatile("cp.async.commit_group;" ::: "memory")
#define CPA_WAIT2()  asm volatile("cp.async.wait_group 2;" ::: "memory")

#define LDSM4(r0, r1, r2, r3, a) \
    asm volatile("ldmatrix.sync.aligned.m8n8.x4.shared.b16 {%0,%1,%2,%3}, [%4];" \
                 : "=r"(r0), "=r"(r1), "=r"(r2), "=r"(r3) : "r"(a))

#define MMAH(d, a, b) \
    asm volatile("mma.sync.aligned.m16n8k16.row.col.f32.f16.f16.f32 " \
                 "{%0,%1,%2,%3}, {%4,%5,%6,%7}, {%8,%9}, {%0,%1,%2,%3};" \
                 : "+f"((d)[0]), "+f"((d)[1]), "+f"((d)[2]), "+f"((d)[3]) \
                 : "r"((a)[0]), "r"((a)[1]), "r"((a)[2]), "r"((a)[3]), \
                   "r"((b)[0]), "r"((b)[1]))

// 2-way scaled fp16 split: v == h + m/4096 + O(2^-24 v)
__device__ __forceinline__ void f16_split2(float v, f16& h, f16& m) {
    h = __float2half_rn(v);
    m = __float2half_rn((v - __half2float(h)) * MSCALE);
}

// ---------------- GEMM: C[M,N] = act(A[M,K] @ W[N,K]^T + bias) ----------------
// A, W given as 2 fp16 planes (h, m/4096). 3-term emulation, dual accumulators:
//   acc_main = sum h*h' ;  acc_s = sum(h*m' + m*h') ;  final = main + s/4096
// CTA tile 128x128, 8 warps (2x4), warp tile 64x32. M tile-exact.
// OUTMODE 0: relu -> 2 f16 planes. OUTMODE 1: tanh -> fp32 (col guard).
template <int OUTMODE>
__global__ __launch_bounds__(256, 1) void gemm_f16e(
    const f16* __restrict__ Ah, const f16* __restrict__ Am, int lda,
    const f16* __restrict__ Wh, const f16* __restrict__ Wm, int ldw,
    const float* __restrict__ bias,
    f16* __restrict__ Ch, f16* __restrict__ Cm, float* __restrict__ Cf,
    int ldc, int N, int nchunks)
{
    extern __shared__ char smem[];
    const uint32_t sb = smem_u32(smem);
    const int tid  = threadIdx.x;
    const int wid  = tid >> 5;
    const int lane = tid & 31;
    const int g    = lane >> 2;
    const int tg   = lane & 3;
    const int wm   = wid & 1;        // 2 row-blocks of 64
    const int wn   = wid >> 1;       // 4 col-blocks of 32
    const int bm   = blockIdx.y * 128;
    const int bn   = blockIdx.x * 128;

    float accm[4][4][4], accs[4][4][4];
#pragma unroll
    for (int i = 0; i < 4; i++)
#pragma unroll
        for (int j = 0; j < 4; j++)
#pragma unroll
            for (int e = 0; e < 4; e++) { accm[i][j][e] = 0.0f; accs[i][j][e] = 0.0f; }

    // ---- stage loader: 2 A planes (128 rows) + 2 W planes (128 rows) ----
    auto load_stage = [&](int buf, int k0) {
        const uint32_t st = sb + buf * STAGE_B;
        const int row4 = tid >> 2;      // 0..63
        const int ch   = tid & 3;       // 4 x 16B = 64B = 32 f16
#pragma unroll
        for (int h = 0; h < 2; ++h) {
            const int row = row4 + h * 64;
            const uint32_t d = st + row * ROWB + ch * 16;
            const size_t srcA = (size_t)(bm + row) * lda + k0 + ch * 8;
            CPA(d,           (const void*)(Ah + srcA), 16);
            CPA(d + A_PLANE, (const void*)(Am + srcA), 16);
            const int n  = bn + row;
            const int pb = (n < N) ? 16 : 0;
            const size_t srcW = (size_t)((n < N) ? n : 0) * ldw + k0 + ch * 8;
            const uint32_t dw = st + W_OFF + row * ROWB + ch * 16;
            CPA(dw,           (const void*)(Wh + srcW), pb);
            CPA(dw + W_PLANE, (const void*)(Wm + srcW), pb);
        }
        CPA_COMMIT();
    };

    const int nT = nchunks;             // chunks of 32 k
    load_stage(0, 0);
    if (nT > 1) load_stage(1, 32); else CPA_COMMIT();

    // ldmatrix per-thread addresses (layout verified in R10/R11):
    const uint32_t a_off = (uint32_t)((wm * 64 + (lane & 15)) * ROWB + (lane >> 4) * 16);
    const int b_row = ((lane >> 4) & 1) * 8 + (lane & 7);
    const int b_ch  = (lane >> 3) & 1;
    const uint32_t b_off = (uint32_t)(W_OFF + (wn * 32 + b_row) * ROWB + b_ch * 16);

    for (int t = 0; t < nT; ++t) {
        if (t + 2 < nT) load_stage((t + 2) % NSTG, (t + 2) * 32);
        else            CPA_COMMIT();
        CPA_WAIT2();
        __syncthreads();

        const uint32_t st = sb + (t % NSTG) * STAGE_B;
#pragma unroll
        for (int ks = 0; ks < 2; ++ks) {
            const uint32_t ko = ks * 32;    // 16 f16
            uint32_t ah[4][4], am[4][4];
            uint32_t bh[4][2], bm_[4][2];
            const uint32_t ab = st + a_off + ko;
#pragma unroll
            for (int mt = 0; mt < 4; ++mt) {
                const uint32_t r = ab + mt * (16 * ROWB);
                LDSM4(ah[mt][0], ah[mt][1], ah[mt][2], ah[mt][3], r);
                LDSM4(am[mt][0], am[mt][1], am[mt][2], am[mt][3], r + A_PLANE);
            }
            const uint32_t bb = st + b_off + ko;
#pragma unroll
            for (int p = 0; p < 2; ++p) {
                const uint32_t r = bb + p * (16 * ROWB);
                LDSM4(bh[2*p][0],  bh[2*p][1],  bh[2*p+1][0],  bh[2*p+1][1],  r);
                LDSM4(bm_[2*p][0], bm_[2*p][1], bm_[2*p+1][0], bm_[2*p+1][1], r + W_PLANE);
            }
#pragma unroll
            for (int mt = 0; mt < 4; ++mt)
#pragma unroll
                for (int nt = 0; nt < 4; ++nt) {
                    MMAH(accm[mt][nt], ah[mt], bh[nt]);     // h*h  -> main
                    MMAH(accs[mt][nt], ah[mt], bm_[nt]);    // h*m  -> scaled
                    MMAH(accs[mt][nt], am[mt], bh[nt]);     // m*h  -> scaled
                }
        }
        __syncthreads();
    }

    // ---- epilogue: final = main + s/4096 ----
#pragma unroll
    for (int nt = 0; nt < 4; ++nt) {
        const int cg = bn + wn * 32 + nt * 8 + tg * 2;
#pragma unroll
        for (int mt = 0; mt < 4; ++mt) {
            const int r0 = bm + wm * 64 + mt * 16 + g;
#pragma unroll
            for (int h = 0; h < 2; ++h) {
                const int r = r0 + h * 8;
                float v0 = fmaf(accs[mt][nt][2*h+0], INV_MSCALE, accm[mt][nt][2*h+0]);
                float v1 = fmaf(accs[mt][nt][2*h+1], INV_MSCALE, accm[mt][nt][2*h+1]);
                if (OUTMODE == 0) {
                    v0 = fmaxf(v0 + bias[cg],     0.0f);
                    v1 = fmaxf(v1 + bias[cg + 1], 0.0f);
                    f16 h0, m0, h1, m1;
                    f16_split2(v0, h0, m0);
                    f16_split2(v1, h1, m1);
                    const size_t gdx = (size_t)r * ldc + cg;
                    __half2 p;
                    p.x = h0; p.y = h1; *(uint32_t*)(Ch + gdx) = *(uint32_t*)&p;
                    p.x = m0; p.y = m1; *(uint32_t*)(Cm + gdx) = *(uint32_t*)&p;
                } else {
                    if (cg < N)     Cf[(size_t)r * ldc + cg]     = tanhf(v0 + bias[cg]);
                    if (cg + 1 < N) Cf[(size_t)r * ldc + cg + 1] = tanhf(v1 + bias[cg + 1]);
                }
            }
        }
    }
}

// ---------------- pre-split kernels ----------------
// seq[:,0:2560]+[2564:3076] -> packed [M,3072] 2 planes
__global__ void split_seq2_kernel(const float* __restrict__ seq,
                                  f16* __restrict__ ph, f16* __restrict__ pm)
{
    const long long t = (long long)blockIdx.x * blockDim.x + threadIdx.x;
    const long long total = (long long)MROWS * SEQC / 8;
    if (t >= total) return;
    const long long e = t * 8;
    const int mr = (int)(e / SEQC);
    const int c0 = (int)(e % SEQC);
    const int src = (c0 < 2560) ? c0 : c0 + 4;
    const float4 v0 = *(const float4*)(seq + (size_t)mr * 3076 + src);
    const float4 v1 = *(const float4*)(seq + (size_t)mr * 3076 + src + 4);
    const float v[8] = {v0.x, v0.y, v0.z, v0.w, v1.x, v1.y, v1.z, v1.w};
    f16 h[8], m[8];
#pragma unroll
    for (int i = 0; i < 8; i++) f16_split2(v[i], h[i], m[i]);
    const size_t d = (size_t)mr * SEQC + c0;
    *(uint4*)(ph + d) = *(uint4*)h;
    *(uint4*)(pm + d) = *(uint4*)m;
}

__global__ void split_w2_kernel(const float* __restrict__ W, int N, int K, int Kp,
                                f16* __restrict__ ph, f16* __restrict__ pm)
{
    const int i = blockIdx.x * blockDim.x + threadIdx.x;
    if (i >= N * Kp) return;
    const int n = i / Kp, k = i % Kp;
    const float v = (k < K) ? W[(size_t)n * K + k] : 0.0f;
    f16 h, m;
    f16_split2(v, h, m);
    ph[i] = h; pm[i] = m;
}

// cc cols [256,260) = relu(pos); [388,448) = 0  (2 planes)
__global__ void pos_pad2_kernel(const float* __restrict__ seq,
                                f16* __restrict__ ph, f16* __restrict__ pm)
{
    const int i = blockIdx.x * blockDim.x + threadIdx.x;
    if (i >= MROWS * 64) return;
    const int mr = i >> 6, j = i & 63;
    float v = 0.0f;
    int col;
    if (j < 4) { v = fmaxf(seq[(size_t)mr * 3076 + 2560 + j], 0.0f); col = 256 + j; }
    else       { col = 384 + j; }
    f16 h, m;
    f16_split2(v, h, m);
    const size_t d = (size_t)mr * 448 + col;
    ph[d] = h; pm[d] = m;
}

// ---------------- Sinkhorn ----------------
__global__ __launch_bounds__(512) void sinkhorn_kernel(
    const float* __restrict__ logits, float* __restrict__ out)
{
    __shared__ float X[36][37];
    __shared__ float red[36];
    const int b = blockIdx.x;
    const int t = threadIdx.x;
    const float* src = logits + (size_t)b * 1296;

    for (int i = t; i < 1296; i += 512)
        X[i / 36][i % 36] = expf(src[i] * TAU_INV);
    __syncthreads();

    for (int it = 0; it < 20; ++it) {
        if (t < 36) {
            float mx = -INFINITY;
#pragma unroll
            for (int c = 0; c < 36; c++) mx = fmaxf(mx, X[t][c]);
            float s = 0.0f;
#pragma unroll
            for (int c = 0; c < 36; c++) s += expf(X[t][c] - mx);
            red[t] = mx + logf(s);
        }
        __syncthreads();
        for (int i = t; i < 1296; i += 512) X[i / 36][i % 36] -= red[i / 36];
        __syncthreads();
        if (t < 36) {
            float mx = -INFINITY;
#pragma unroll
            for (int r = 0; r < 36; r++) mx = fmaxf(mx, X[r][t]);
            float s = 0.0f;
#pragma unroll
            for (int r = 0; r < 36; r++) s += expf(X[r][t] - mx);
            red[t] = mx + logf(s);
        }
        __syncthreads();
        for (int i = t; i < 1296; i += 512) X[i / 36][i % 36] -= red[i % 36];
        __syncthreads();
    }
    for (int i = t; i < 1296; i += 512)
        out[(size_t)b * 1296 + i] = expf(X[i / 36][i % 36]);
}

// ---------------- host ----------------
extern "C" void kernel_launch(void* const* d_in, const int* in_sizes, int n_in,
                              void* d_out, int out_size)
{
    const float* seq   = (const float*)d_in[0];
    const float* W1t_w = (const float*)d_in[1];
    const float* W1t_b = (const float*)d_in[2];
    const float* W1v_w = (const float*)d_in[3];
    const float* W1v_b = (const float*)d_in[4];
    const float* W2v_w = (const float*)d_in[5];
    const float* W2v_b = (const float*)d_in[6];
    const float* W1s_w = (const float*)d_in[7];
    const float* W1s_b = (const float*)d_in[8];
    const float* Wfp_w = (const float*)d_in[9];
    const float* Wfp_b = (const float*)d_in[10];
    const float* Wfc_w = (const float*)d_in[11];
    const float* Wfc_b = (const float*)d_in[12];
    float* out = (float*)d_out;

    f16 *sq[2], *xv[2], *cc[2], *a3[2], *wp[2];
    float* logits;
    {
        f16* p;
        cudaGetSymbolAddress((void**)&p, g_seqP);
        sq[0] = p; sq[1] = p + (size_t)MROWS * SEQC;
        cudaGetSymbolAddress((void**)&p, g_xvP);
        xv[0] = p; xv[1] = p + (size_t)MROWS * 512;
        cudaGetSymbolAddress((void**)&p, g_ccP);
        cc[0] = p; cc[1] = p + (size_t)MROWS * 448;
        cudaGetSymbolAddress((void**)&p, g_a3P);
        a3[0] = p; a3[1] = p + (size_t)MROWS * 256;
        cudaGetSymbolAddress((void**)&p, g_wP);
        const size_t wsz = 128*512 + 512*2048 + 128*512 + 128*512 + 256*448 + 36*256;
        wp[0] = p; wp[1] = p + wsz;
        cudaGetSymbolAddress((void**)&logits, g_logits);
    }

    cudaFuncSetAttribute(gemm_f16e<0>, cudaFuncAttributeMaxDynamicSharedMemorySize, GEMM_SMEM);
    cudaFuncSetAttribute(gemm_f16e<1>, cudaFuncAttributeMaxDynamicSharedMemorySize, GEMM_SMEM);

    // ---- splits ----
    {
        const long long n = (long long)MROWS * SEQC / 8;
        split_seq2_kernel<<<(unsigned)((n + 255) / 256), 256>>>(seq, sq[0], sq[1]);
    }
    split_w2_kernel<<<(128*512  + 255) / 256, 256>>>(W1t_w, 128, 512, 512,
        wp[0] + WOFF_TXT,  wp[1] + WOFF_TXT);
    split_w2_kernel<<<(512*2048 + 255) / 256, 256>>>(W1v_w, 512, 2048, 2048,
        wp[0] + WOFF_VIS1, wp[1] + WOFF_VIS1);
    split_w2_kernel<<<(128*512  + 255) / 256, 256>>>(W2v_w, 128, 512, 512,
        wp[0] + WOFF_VIS2, wp[1] + WOFF_VIS2);
    split_w2_kernel<<<(128*512  + 255) / 256, 256>>>(W1s_w, 128, 512, 512,
        wp[0] + WOFF_SEN,  wp[1] + WOFF_SEN);
    split_w2_kernel<<<(256*448  + 255) / 256, 256>>>(Wfp_w, 256, 388, 448,
        wp[0] + WOFF_FCP,  wp[1] + WOFF_FCP);
    split_w2_kernel<<<(36*256   + 255) / 256, 256>>>(Wfc_w, 36, 256, 256,
        wp[0] + WOFF_FC,   wp[1] + WOFF_FC);
    pos_pad2_kernel<<<(MROWS * 64 + 255) / 256, 256>>>(seq, cc[0], cc[1]);

    const int mT = MROWS / 128;   // 144

    // vis1: K=2048 -> xv [M,512]
    gemm_f16e<0><<<dim3(4, mT), 256, GEMM_SMEM>>>(
        sq[0] + 512, sq[1] + 512, SEQC,
        wp[0] + WOFF_VIS1, wp[1] + WOFF_VIS1, 2048, W1v_b,
        xv[0], xv[1], nullptr, 512, 512, 64);
    // txt: K=512 -> cc cols [0,128)
    gemm_f16e<0><<<dim3(1, mT), 256, GEMM_SMEM>>>(
        sq[0], sq[1], SEQC,
        wp[0] + WOFF_TXT, wp[1] + WOFF_TXT, 512, W1t_b,
        cc[0], cc[1], nullptr, 448, 128, 16);
    // sen: K=512 -> cc cols [260,388)
    gemm_f16e<0><<<dim3(1, mT), 256, GEMM_SMEM>>>(
        sq[0] + 2560, sq[1] + 2560, SEQC,
        wp[0] + WOFF_SEN, wp[1] + WOFF_SEN, 512, W1s_b,
        cc[0] + 260, cc[1] + 260, nullptr, 448, 128, 16);
    // vis2: K=512 -> cc cols [128,256)
    gemm_f16e<0><<<dim3(1, mT), 256, GEMM_SMEM>>>(
        xv[0], xv[1], 512,
        wp[0] + WOFF_VIS2, wp[1] + WOFF_VIS2, 512, W2v_b,
        cc[0] + 128, cc[1] + 128, nullptr, 448, 128, 16);
    // fc_pos: K=448 -> a3 [M,256]
    gemm_f16e<0><<<dim3(2, mT), 256, GEMM_SMEM>>>(
        cc[0], cc[1], 448,
        wp[0] + WOFF_FCP, wp[1] + WOFF_FCP, 448, Wfp_b,
        a3[0], a3[1], nullptr, 256, 256, 14);
    // fc: K=256 -> logits [M,36], tanh
    gemm_f16e<1><<<dim3(1, mT), 256, GEMM_SMEM>>>(
        a3[0], a3[1], 256,
        wp[0] + WOFF_FC, wp[1] + WOFF_FC, 256, Wfc_b,
        nullptr, nullptr, logits, 36, 36, 8);

    sinkhorn_kernel<<<512, 512>>>(logits, out);
}

// round 13
// speedup vs baseline: 3.5387x; 1.1117x over previous
#include <cuda_runtime.h>
#include <cuda_fp16.h>
#include <math.h>
#include <stdint.h>

#define MROWS 18432
#define TAU_INV 20.0f
#define MSCALE 4096.0f
#define INV_MSCALE (1.0f / 4096.0f)

typedef __half f16;

// ---------------- scratch (device globals; alloc-free) ----------------
// 2 fp16 planes (h, m) per tensor: v == h + m/4096 + O(2^-24 v)
#define SEQC 3072
__device__ __align__(128) f16 g_seqP[2][(size_t)MROWS * SEQC];
__device__ __align__(128) f16 g_xvP [2][(size_t)MROWS * 512];
__device__ __align__(128) f16 g_ccP [2][(size_t)MROWS * 448];
__device__ __align__(128) f16 g_a3P [2][(size_t)MROWS * 256];
__device__ __align__(128) f16 g_wP  [2][128*512 + 512*2048 + 128*512 + 128*512 + 256*448 + 36*256];
__device__ __align__(128) float g_logits[(size_t)MROWS * 36];

#define WOFF_TXT   0
#define WOFF_VIS1  (WOFF_TXT  + 128*512)
#define WOFF_VIS2  (WOFF_VIS1 + 512*2048)
#define WOFF_SEN   (WOFF_VIS2 + 128*512)
#define WOFF_FCP   (WOFF_SEN  + 128*512)
#define WOFF_FC    (WOFF_FCP  + 256*448)

// ---------------- smem layout ----------------
// row: 64 data f16 (128B) + 16B pad = 144B. 144 mod 128 = 16 -> 8 consecutive
// rows land in 8 distinct 16B bank-groups: ldmatrix conflict-free.
#define ROWB    144
#define A_PLANE (128 * ROWB)           // 18432
#define W_PLANE (128 * ROWB)           // 18432
#define W_OFF   (2 * A_PLANE)          // 36864
#define STAGE_B (2 * A_PLANE + 2 * W_PLANE)   // 73728
#define NSTG    3
#define GEMM_SMEM (NSTG * STAGE_B)     // 221184

// ---------------- PTX helpers ----------------
__device__ __forceinline__ uint32_t smem_u32(const void* p) {
    uint32_t a;
    asm("{ .reg .u64 t; cvta.to.shared.u64 t, %1; cvt.u32.u64 %0, t; }" : "=r"(a) : "l"(p));
    return a;
}

#define CPA(dst, src, pb) \
    asm volatile("cp.async.cg.shared.global [%0], [%1], 16, %2;" \
                 :: "r"(dst), "l"(src), "r"(pb) : "memory")
#define CPA_COMMIT() asm volatile("cp.async.commit_group;" ::: "memory")
#define CPA_WAIT2()  asm volatile("cp.async.wait_group 2;" ::: "memory")

#define LDSM4(r0, r1, r2, r3, a) \
    asm volatile("ldmatrix.sync.aligned.m8n8.x4.shared.b16 {%0,%1,%2,%3}, [%4];" \
                 : "=r"(r0), "=r"(r1), "=r"(r2), "=r"(r3) : "r"(a))

#define MMAH(d, a, b) \
    asm volatile("mma.sync.aligned.m16n8k16.row.col.f32.f16.f16.f32 " \
                 "{%0,%1,%2,%3}, {%4,%5,%6,%7}, {%8,%9}, {%0,%1,%2,%3};" \
                 : "+f"((d)[0]), "+f"((d)[1]), "+f"((d)[2]), "+f"((d)[3]) \
                 : "r"((a)[0]), "r"((a)[1]), "r"((a)[2]), "r"((a)[3]), \
                   "r"((b)[0]), "r"((b)[1]))

// 2-way scaled fp16 split: v == h + m/4096 + O(2^-24 v)
__device__ __forceinline__ void f16_split2(float v, f16& h, f16& m) {
    h = __float2half_rn(v);
    m = __float2half_rn((v - __half2float(h)) * MSCALE);
}

// ---------------- GEMM: C[M,N] = act(A[M,K] @ W[N,K]^T + bias) ----------------
// A, W given as 2 fp16 planes (h, m/4096). 3-term emulation, dual accumulators:
//   acc_main = sum h*h' ;  acc_s = sum(h*m' + m*h') ;  final = main + s/4096
// CTA tile 128x128, 8 warps (2x4), warp tile 64x32. K chunks of 64. M tile-exact.
// OUTMODE 0: relu -> 2 f16 planes. OUTMODE 1: tanh -> fp32 (col guard).
template <int OUTMODE>
__global__ __launch_bounds__(256, 1) void gemm_f16e(
    const f16* __restrict__ Ah, const f16* __restrict__ Am, int lda,
    const f16* __restrict__ Wh, const f16* __restrict__ Wm, int ldw,
    const float* __restrict__ bias,
    f16* __restrict__ Ch, f16* __restrict__ Cm, float* __restrict__ Cf,
    int ldc, int N, int nchunks)
{
    extern __shared__ char smem[];
    const uint32_t sb = smem_u32(smem);
    const int tid  = threadIdx.x;
    const int wid  = tid >> 5;
    const int lane = tid & 31;
    const int g    = lane >> 2;
    const int tg   = lane & 3;
    const int wm   = wid & 1;        // 2 row-blocks of 64
    const int wn   = wid >> 1;       // 4 col-blocks of 32
    const int bm   = blockIdx.y * 128;
    const int bn   = blockIdx.x * 128;

    float accm[4][4][4], accs[4][4][4];
#pragma unroll
    for (int i = 0; i < 4; i++)
#pragma unroll
        for (int j = 0; j < 4; j++)
#pragma unroll
            for (int e = 0; e < 4; e++) { accm[i][j][e] = 0.0f; accs[i][j][e] = 0.0f; }

    // ---- stage loader: 2 A planes + 2 W planes, 128 rows x 8 chunks of 16B ----
    auto load_stage = [&](int buf, int k0) {
        const uint32_t st = sb + buf * STAGE_B;
#pragma unroll
        for (int j = 0; j < 4; ++j) {
            const int e   = tid + 256 * j;     // 0..1023
            const int row = e >> 3;            // 0..127
            const int ch  = e & 7;             // 8 x 16B = 128B = 64 f16
            const uint32_t d = st + row * ROWB + ch * 16;
            const size_t srcA = (size_t)(bm + row) * lda + k0 + ch * 8;
            CPA(d,           (const void*)(Ah + srcA), 16);
            CPA(d + A_PLANE, (const void*)(Am + srcA), 16);
            const int n  = bn + row;
            const int pb = (n < N) ? 16 : 0;
            const size_t srcW = (size_t)((n < N) ? n : 0) * ldw + k0 + ch * 8;
            const uint32_t dw = st + W_OFF + row * ROWB + ch * 16;
            CPA(dw,           (const void*)(Wh + srcW), pb);
            CPA(dw + W_PLANE, (const void*)(Wm + srcW), pb);
        }
        CPA_COMMIT();
    };

    const int nT = nchunks;             // chunks of 64 k
    load_stage(0, 0);
    if (nT > 1) load_stage(1, 64); else CPA_COMMIT();

    // ldmatrix per-thread addresses (row pattern verified R10-R12):
    const uint32_t a_off = (uint32_t)((wm * 64 + (lane & 15)) * ROWB + (lane >> 4) * 16);
    const int b_row = ((lane >> 4) & 1) * 8 + (lane & 7);
    const int b_ch  = (lane >> 3) & 1;
    const uint32_t b_off = (uint32_t)(W_OFF + (wn * 32 + b_row) * ROWB + b_ch * 16);

    for (int t = 0; t < nT; ++t) {
        if (t + 2 < nT) load_stage((t + 2) % NSTG, (t + 2) * 64);
        else            CPA_COMMIT();
        CPA_WAIT2();
        __syncthreads();

        const uint32_t st = sb + (t % NSTG) * STAGE_B;
#pragma unroll
        for (int ks = 0; ks < 4; ++ks) {
            const uint32_t ko = ks * 32;    // 16 f16 = 32B per k16-step
            uint32_t ah[4][4], am[4][4];
            uint32_t bh[4][2], bm_[4][2];
            const uint32_t ab = st + a_off + ko;
#pragma unroll
            for (int mt = 0; mt < 4; ++mt) {
                const uint32_t r = ab + mt * (16 * ROWB);
                LDSM4(ah[mt][0], ah[mt][1], ah[mt][2], ah[mt][3], r);
                LDSM4(am[mt][0], am[mt][1], am[mt][2], am[mt][3], r + A_PLANE);
            }
            const uint32_t bb = st + b_off + ko;
#pragma unroll
            for (int p = 0; p < 2; ++p) {
                const uint32_t r = bb + p * (16 * ROWB);
                LDSM4(bh[2*p][0],  bh[2*p][1],  bh[2*p+1][0],  bh[2*p+1][1],  r);
                LDSM4(bm_[2*p][0], bm_[2*p][1], bm_[2*p+1][0], bm_[2*p+1][1], r + W_PLANE);
            }
#pragma unroll
            for (int mt = 0; mt < 4; ++mt)
#pragma unroll
                for (int nt = 0; nt < 4; ++nt) {
                    MMAH(accm[mt][nt], ah[mt], bh[nt]);     // h*h  -> main
                    MMAH(accs[mt][nt], ah[mt], bm_[nt]);    // h*m  -> scaled
                    MMAH(accs[mt][nt], am[mt], bh[nt]);     // m*h  -> scaled
                }
        }
        __syncthreads();
    }

    // ---- epilogue: final = main + s/4096 ----
#pragma unroll
    for (int nt = 0; nt < 4; ++nt) {
        const int cg = bn + wn * 32 + nt * 8 + tg * 2;
#pragma unroll
        for (int mt = 0; mt < 4; ++mt) {
            const int r0 = bm + wm * 64 + mt * 16 + g;
#pragma unroll
            for (int h = 0; h < 2; ++h) {
                const int r = r0 + h * 8;
                float v0 = fmaf(accs[mt][nt][2*h+0], INV_MSCALE, accm[mt][nt][2*h+0]);
                float v1 = fmaf(accs[mt][nt][2*h+1], INV_MSCALE, accm[mt][nt][2*h+1]);
                if (OUTMODE == 0) {
                    v0 = fmaxf(v0 + bias[cg],     0.0f);
                    v1 = fmaxf(v1 + bias[cg + 1], 0.0f);
                    f16 h0, m0, h1, m1;
                    f16_split2(v0, h0, m0);
                    f16_split2(v1, h1, m1);
                    const size_t gdx = (size_t)r * ldc + cg;
                    __half2 p;
                    p.x = h0; p.y = h1; *(uint32_t*)(Ch + gdx) = *(uint32_t*)&p;
                    p.x = m0; p.y = m1; *(uint32_t*)(Cm + gdx) = *(uint32_t*)&p;
                } else {
                    if (cg < N)     Cf[(size_t)r * ldc + cg]     = tanhf(v0 + bias[cg]);
                    if (cg + 1 < N) Cf[(size_t)r * ldc + cg + 1] = tanhf(v1 + bias[cg + 1]);
                }
            }
        }
    }
}

// ---------------- pre-split kernels ----------------
// seq[:,0:2560]+[2564:3076] -> packed [M,3072] 2 planes
__global__ void split_seq2_kernel(const float* __restrict__ seq,
                                  f16* __restrict__ ph, f16* __restrict__ pm)
{
    const long long t = (long long)blockIdx.x * blockDim.x + threadIdx.x;
    const long long total = (long long)MROWS * SEQC / 8;
    if (t >= total) return;
    const long long e = t * 8;
    const int mr = (int)(e / SEQC);
    const int c0 = (int)(e % SEQC);
    const int src = (c0 < 2560) ? c0 : c0 + 4;
    const float4 v0 = *(const float4*)(seq + (size_t)mr * 3076 + src);
    const float4 v1 = *(const float4*)(seq + (size_t)mr * 3076 + src + 4);
    const float v[8] = {v0.x, v0.y, v0.z, v0.w, v1.x, v1.y, v1.z, v1.w};
    f16 h[8], m[8];
#pragma unroll
    for (int i = 0; i < 8; i++) f16_split2(v[i], h[i], m[i]);
    const size_t d = (size_t)mr * SEQC + c0;
    *(uint4*)(ph + d) = *(uint4*)h;
    *(uint4*)(pm + d) = *(uint4*)m;
}

__global__ void split_w2_kernel(const float* __restrict__ W, int N, int K, int Kp,
                                f16* __restrict__ ph, f16* __restrict__ pm)
{
    const int i = blockIdx.x * blockDim.x + threadIdx.x;
    if (i >= N * Kp) return;
    const int n = i / Kp, k = i % Kp;
    const float v = (k < K) ? W[(size_t)n * K + k] : 0.0f;
    f16 h, m;
    f16_split2(v, h, m);
    ph[i] = h; pm[i] = m;
}

// cc cols [256,260) = relu(pos); [388,448) = 0  (2 planes)
__global__ void pos_pad2_kernel(const float* __restrict__ seq,
                                f16* __restrict__ ph, f16* __restrict__ pm)
{
    const int i = blockIdx.x * blockDim.x + threadIdx.x;
    if (i >= MROWS * 64) return;
    const int mr = i >> 6, j = i & 63;
    float v = 0.0f;
    int col;
    if (j < 4) { v = fmaxf(seq[(size_t)mr * 3076 + 2560 + j], 0.0f); col = 256 + j; }
    else       { col = 384 + j; }
    f16 h, m;
    f16_split2(v, h, m);
    const size_t d = (size_t)mr * 448 + col;
    ph[d] = h; pm[d] = m;
}

// ---------------- Sinkhorn ----------------
__global__ __launch_bounds__(512) void sinkhorn_kernel(
    const float* __restrict__ logits, float* __restrict__ out)
{
    __shared__ float X[36][37];
    __shared__ float red[36];
    const int b = blockIdx.x;
    const int t = threadIdx.x;
    const float* src = logits + (size_t)b * 1296;

    for (int i = t; i < 1296; i += 512)
        X[i / 36][i % 36] = expf(src[i] * TAU_INV);
    __syncthreads();

    for (int it = 0; it < 20; ++it) {
        if (t < 36) {
            float mx = -INFINITY;
#pragma unroll
            for (int c = 0; c < 36; c++) mx = fmaxf(mx, X[t][c]);
            float s = 0.0f;
#pragma unroll
            for (int c = 0; c < 36; c++) s += expf(X[t][c] - mx);
            red[t] = mx + logf(s);
        }
        __syncthreads();
        for (int i = t; i < 1296; i += 512) X[i / 36][i % 36] -= red[i / 36];
        __syncthreads();
        if (t < 36) {
            float mx = -INFINITY;
#pragma unroll
            for (int r = 0; r < 36; r++) mx = fmaxf(mx, X[r][t]);
            float s = 0.0f;
#pragma unroll
            for (int r = 0; r < 36; r++) s += expf(X[r][t] - mx);
            red[t] = mx + logf(s);
        }
        __syncthreads();
        for (int i = t; i < 1296; i += 512) X[i / 36][i % 36] -= red[i % 36];
        __syncthreads();
    }
    for (int i = t; i < 1296; i += 512)
        out[(size_t)b * 1296 + i] = expf(X[i / 36][i % 36]);
}

// ---------------- host ----------------
extern "C" void kernel_launch(void* const* d_in, const int* in_sizes, int n_in,
                              void* d_out, int out_size)
{
    const float* seq   = (const float*)d_in[0];
    const float* W1t_w = (const float*)d_in[1];
    const float* W1t_b = (const float*)d_in[2];
    const float* W1v_w = (const float*)d_in[3];
    const float* W1v_b = (const float*)d_in[4];
    const float* W2v_w = (const float*)d_in[5];
    const float* W2v_b = (const float*)d_in[6];
    const float* W1s_w = (const float*)d_in[7];
    const float* W1s_b = (const float*)d_in[8];
    const float* Wfp_w = (const float*)d_in[9];
    const float* Wfp_b = (const float*)d_in[10];
    const float* Wfc_w = (const float*)d_in[11];
    const float* Wfc_b = (const float*)d_in[12];
    float* out = (float*)d_out;

    f16 *sq[2], *xv[2], *cc[2], *a3[2], *wp[2];
    float* logits;
    {
        f16* p;
        cudaGetSymbolAddress((void**)&p, g_seqP);
        sq[0] = p; sq[1] = p + (size_t)MROWS * SEQC;
        cudaGetSymbolAddress((void**)&p, g_xvP);
        xv[0] = p; xv[1] = p + (size_t)MROWS * 512;
        cudaGetSymbolAddress((void**)&p, g_ccP);
        cc[0] = p; cc[1] = p + (size_t)MROWS * 448;
        cudaGetSymbolAddress((void**)&p, g_a3P);
        a3[0] = p; a3[1] = p + (size_t)MROWS * 256;
        cudaGetSymbolAddress((void**)&p, g_wP);
        const size_t wsz = 128*512 + 512*2048 + 128*512 + 128*512 + 256*448 + 36*256;
        wp[0] = p; wp[1] = p + wsz;
        cudaGetSymbolAddress((void**)&logits, g_logits);
    }

    cudaFuncSetAttribute(gemm_f16e<0>, cudaFuncAttributeMaxDynamicSharedMemorySize, GEMM_SMEM);
    cudaFuncSetAttribute(gemm_f16e<1>, cudaFuncAttributeMaxDynamicSharedMemorySize, GEMM_SMEM);

    // ---- splits ----
    {
        const long long n = (long long)MROWS * SEQC / 8;
        split_seq2_kernel<<<(unsigned)((n + 255) / 256), 256>>>(seq, sq[0], sq[1]);
    }
    split_w2_kernel<<<(128*512  + 255) / 256, 256>>>(W1t_w, 128, 512, 512,
        wp[0] + WOFF_TXT,  wp[1] + WOFF_TXT);
    split_w2_kernel<<<(512*2048 + 255) / 256, 256>>>(W1v_w, 512, 2048, 2048,
        wp[0] + WOFF_VIS1, wp[1] + WOFF_VIS1);
    split_w2_kernel<<<(128*512  + 255) / 256, 256>>>(W2v_w, 128, 512, 512,
        wp[0] + WOFF_VIS2, wp[1] + WOFF_VIS2);
    split_w2_kernel<<<(128*512  + 255) / 256, 256>>>(W1s_w, 128, 512, 512,
        wp[0] + WOFF_SEN,  wp[1] + WOFF_SEN);
    split_w2_kernel<<<(256*448  + 255) / 256, 256>>>(Wfp_w, 256, 388, 448,
        wp[0] + WOFF_FCP,  wp[1] + WOFF_FCP);
    split_w2_kernel<<<(36*256   + 255) / 256, 256>>>(Wfc_w, 36, 256, 256,
        wp[0] + WOFF_FC,   wp[1] + WOFF_FC);
    pos_pad2_kernel<<<(MROWS * 64 + 255) / 256, 256>>>(seq, cc[0], cc[1]);

    const int mT = MROWS / 128;   // 144

    // vis1: K=2048 -> xv [M,512]   (32 chunks of 64)
    gemm_f16e<0><<<dim3(4, mT), 256, GEMM_SMEM>>>(
        sq[0] + 512, sq[1] + 512, SEQC,
        wp[0] + WOFF_VIS1, wp[1] + WOFF_VIS1, 2048, W1v_b,
        xv[0], xv[1], nullptr, 512, 512, 32);
    // txt: K=512 -> cc cols [0,128)   (8 chunks)
    gemm_f16e<0><<<dim3(1, mT), 256, GEMM_SMEM>>>(
        sq[0], sq[1], SEQC,
        wp[0] + WOFF_TXT, wp[1] + WOFF_TXT, 512, W1t_b,
        cc[0], cc[1], nullptr, 448, 128, 8);
    // sen: K=512 -> cc cols [260,388)   (8 chunks)
    gemm_f16e<0><<<dim3(1, mT), 256, GEMM_SMEM>>>(
        sq[0] + 2560, sq[1] + 2560, SEQC,
        wp[0] + WOFF_SEN, wp[1] + WOFF_SEN, 512, W1s_b,
        cc[0] + 260, cc[1] + 260, nullptr, 448, 128, 8);
    // vis2: K=512 -> cc cols [128,256)   (8 chunks)
    gemm_f16e<0><<<dim3(1, mT), 256, GEMM_SMEM>>>(
        xv[0], xv[1], 512,
        wp[0] + WOFF_VIS2, wp[1] + WOFF_VIS2, 512, W2v_b,
        cc[0] + 128, cc[1] + 128, nullptr, 448, 128, 8);
    // fc_pos: K=448 -> a3 [M,256]   (7 chunks)
    gemm_f16e<0><<<dim3(2, mT), 256, GEMM_SMEM>>>(
        cc[0], cc[1], 448,
        wp[0] + WOFF_FCP, wp[1] + WOFF_FCP, 448, Wfp_b,
        a3[0], a3[1], nullptr, 256, 256, 7);
    // fc: K=256 -> logits [M,36], tanh   (4 chunks)
    gemm_f16e<1><<<dim3(1, mT), 256, GEMM_SMEM>>>(
        a3[0], a3[1], 256,
        wp[0] + WOFF_FC, wp[1] + WOFF_FC, 256, Wfc_b,
        nullptr, nullptr, logits, 36, 36, 4);

    sinkhorn_kernel<<<512, 512>>>(logits, out);
}

// round 14
// speedup vs baseline: 3.6175x; 1.0223x over previous
#include <cuda_runtime.h>
#include <cuda_fp16.h>
#include <math.h>
#include <stdint.h>

#define MROWS 18432
#define TAU_INV 20.0f
#define MSCALE 4096.0f
#define INV_MSCALE (1.0f / 4096.0f)

typedef __half f16;

// ---------------- scratch (device globals; alloc-free) ----------------
#define SEQC 3072
__device__ __align__(128) f16 g_seqP[2][(size_t)MROWS * SEQC];
__device__ __align__(128) f16 g_xvP [2][(size_t)MROWS * 512];
__device__ __align__(128) f16 g_ccP [2][(size_t)MROWS * 448];
__device__ __align__(128) f16 g_a3P [2][(size_t)MROWS * 256];
__device__ __align__(128) f16 g_wP  [2][128*512 + 512*2048 + 128*512 + 128*512 + 256*448 + 36*256];
__device__ __align__(128) float g_logits[(size_t)MROWS * 36];

#define WOFF_TXT   0
#define WOFF_VIS1  (WOFF_TXT  + 128*512)
#define WOFF_VIS2  (WOFF_VIS1 + 512*2048)
#define WOFF_SEN   (WOFF_VIS2 + 128*512)
#define WOFF_FCP   (WOFF_SEN  + 128*512)
#define WOFF_FC    (WOFF_FCP  + 256*448)

// ---------------- smem layout ----------------
// row: 64 data f16 (128B) + 16B pad = 144B -> ldmatrix conflict-free.
#define ROWB    144
#define A_PLANE (128 * ROWB)
#define W_PLANE (128 * ROWB)
#define W_OFF   (2 * A_PLANE)
#define STAGE_B (2 * A_PLANE + 2 * W_PLANE)   // 73728
#define NSTG    3
#define GEMM_SMEM (NSTG * STAGE_B)            // 221184

// ---------------- PTX helpers ----------------
__device__ __forceinline__ uint32_t smem_u32(const void* p) {
    uint32_t a;
    asm("{ .reg .u64 t; cvta.to.shared.u64 t, %1; cvt.u32.u64 %0, t; }" : "=r"(a) : "l"(p));
    return a;
}

#define CPA(dst, src, pb) \
    asm volatile("cp.async.cg.shared.global [%0], [%1], 16, %2;" \
                 :: "r"(dst), "l"(src), "r"(pb) : "memory")
#define CPA_COMMIT() asm volatile("cp.async.commit_group;" ::: "memory")
#define CPA_WAIT2()  asm volatile("cp.async.wait_group 2;" ::: "memory")

#define LDSM4(r0, r1, r2, r3, a) \
    asm volatile("ldmatrix.sync.aligned.m8n8.x4.shared.b16 {%0,%1,%2,%3}, [%4];" \
                 : "=r"(r0), "=r"(r1), "=r"(r2), "=r"(r3) : "r"(a))

#define MMAH(d, a, b) \
    asm volatile("mma.sync.aligned.m16n8k16.row.col.f32.f16.f16.f32 " \
                 "{%0,%1,%2,%3}, {%4,%5,%6,%7}, {%8,%9}, {%0,%1,%2,%3};" \
                 : "+f"((d)[0]), "+f"((d)[1]), "+f"((d)[2]), "+f"((d)[3]) \
                 : "r"((a)[0]), "r"((a)[1]), "r"((a)[2]), "r"((a)[3]), \
                   "r"((b)[0]), "r"((b)[1]))

// 2-way scaled fp16 split: v == h + m/4096 + O(2^-24 v)
__device__ __forceinline__ void f16_split2(float v, f16& h, f16& m) {
    h = __float2half_rn(v);
    m = __float2half_rn((v - __half2float(h)) * MSCALE);
}

// ---------------- GEMM (identical to R13) ----------------
template <int OUTMODE>
__global__ __launch_bounds__(256, 1) void gemm_f16e(
    const f16* __restrict__ Ah, const f16* __restrict__ Am, int lda,
    const f16* __restrict__ Wh, const f16* __restrict__ Wm, int ldw,
    const float* __restrict__ bias,
    f16* __restrict__ Ch, f16* __restrict__ Cm, float* __restrict__ Cf,
    int ldc, int N, int nchunks)
{
    extern __shared__ char smem[];
    const uint32_t sb = smem_u32(smem);
    const int tid  = threadIdx.x;
    const int wid  = tid >> 5;
    const int lane = tid & 31;
    const int g    = lane >> 2;
    const int tg   = lane & 3;
    const int wm   = wid & 1;
    const int wn   = wid >> 1;
    const int bm   = blockIdx.y * 128;
    const int bn   = blockIdx.x * 128;

    float accm[4][4][4], accs[4][4][4];
#pragma unroll
    for (int i = 0; i < 4; i++)
#pragma unroll
        for (int j = 0; j < 4; j++)
#pragma unroll
            for (int e = 0; e < 4; e++) { accm[i][j][e] = 0.0f; accs[i][j][e] = 0.0f; }

    auto load_stage = [&](int buf, int k0) {
        const uint32_t st = sb + buf * STAGE_B;
#pragma unroll
        for (int j = 0; j < 4; ++j) {
            const int e   = tid + 256 * j;
            const int row = e >> 3;
            const int ch  = e & 7;
            const uint32_t d = st + row * ROWB + ch * 16;
            const size_t srcA = (size_t)(bm + row) * lda + k0 + ch * 8;
            CPA(d,           (const void*)(Ah + srcA), 16);
            CPA(d + A_PLANE, (const void*)(Am + srcA), 16);
            const int n  = bn + row;
            const int pb = (n < N) ? 16 : 0;
            const size_t srcW = (size_t)((n < N) ? n : 0) * ldw + k0 + ch * 8;
            const uint32_t dw = st + W_OFF + row * ROWB + ch * 16;
            CPA(dw,           (const void*)(Wh + srcW), pb);
            CPA(dw + W_PLANE, (const void*)(Wm + srcW), pb);
        }
        CPA_COMMIT();
    };

    const int nT = nchunks;
    load_stage(0, 0);
    if (nT > 1) load_stage(1, 64); else CPA_COMMIT();

    const uint32_t a_off = (uint32_t)((wm * 64 + (lane & 15)) * ROWB + (lane >> 4) * 16);
    const int b_row = ((lane >> 4) & 1) * 8 + (lane & 7);
    const int b_ch  = (lane >> 3) & 1;
    const uint32_t b_off = (uint32_t)(W_OFF + (wn * 32 + b_row) * ROWB + b_ch * 16);

    for (int t = 0; t < nT; ++t) {
        if (t + 2 < nT) load_stage((t + 2) % NSTG, (t + 2) * 64);
        else            CPA_COMMIT();
        CPA_WAIT2();
        __syncthreads();

        const uint32_t st = sb + (t % NSTG) * STAGE_B;
#pragma unroll
        for (int ks = 0; ks < 4; ++ks) {
            const uint32_t ko = ks * 32;
            uint32_t ah[4][4], am[4][4];
            uint32_t bh[4][2], bm_[4][2];
            const uint32_t ab = st + a_off + ko;
#pragma unroll
            for (int mt = 0; mt < 4; ++mt) {
                const uint32_t r = ab + mt * (16 * ROWB);
                LDSM4(ah[mt][0], ah[mt][1], ah[mt][2], ah[mt][3], r);
                LDSM4(am[mt][0], am[mt][1], am[mt][2], am[mt][3], r + A_PLANE);
            }
            const uint32_t bb = st + b_off + ko;
#pragma unroll
            for (int p = 0; p < 2; ++p) {
                const uint32_t r = bb + p * (16 * ROWB);
                LDSM4(bh[2*p][0],  bh[2*p][1],  bh[2*p+1][0],  bh[2*p+1][1],  r);
                LDSM4(bm_[2*p][0], bm_[2*p][1], bm_[2*p+1][0], bm_[2*p+1][1], r + W_PLANE);
            }
#pragma unroll
            for (int mt = 0; mt < 4; ++mt)
#pragma unroll
                for (int nt = 0; nt < 4; ++nt) {
                    MMAH(accm[mt][nt], ah[mt], bh[nt]);
                    MMAH(accs[mt][nt], ah[mt], bm_[nt]);
                    MMAH(accs[mt][nt], am[mt], bh[nt]);
                }
        }
        __syncthreads();
    }

#pragma unroll
    for (int nt = 0; nt < 4; ++nt) {
        const int cg = bn + wn * 32 + nt * 8 + tg * 2;
#pragma unroll
        for (int mt = 0; mt < 4; ++mt) {
            const int r0 = bm + wm * 64 + mt * 16 + g;
#pragma unroll
            for (int h = 0; h < 2; ++h) {
                const int r = r0 + h * 8;
                float v0 = fmaf(accs[mt][nt][2*h+0], INV_MSCALE, accm[mt][nt][2*h+0]);
                float v1 = fmaf(accs[mt][nt][2*h+1], INV_MSCALE, accm[mt][nt][2*h+1]);
                if (OUTMODE == 0) {
                    v0 = fmaxf(v0 + bias[cg],     0.0f);
                    v1 = fmaxf(v1 + bias[cg + 1], 0.0f);
                    f16 h0, m0, h1, m1;
                    f16_split2(v0, h0, m0);
                    f16_split2(v1, h1, m1);
                    const size_t gdx = (size_t)r * ldc + cg;
                    __half2 p;
                    p.x = h0; p.y = h1; *(uint32_t*)(Ch + gdx) = *(uint32_t*)&p;
                    p.x = m0; p.y = m1; *(uint32_t*)(Cm + gdx) = *(uint32_t*)&p;
                } else {
                    if (cg < N)     Cf[(size_t)r * ldc + cg]     = tanhf(v0 + bias[cg]);
                    if (cg + 1 < N) Cf[(size_t)r * ldc + cg + 1] = tanhf(v1 + bias[cg + 1]);
                }
            }
        }
    }
}

// ---------------- pre-split kernels ----------------
__global__ void split_seq2_kernel(const float* __restrict__ seq,
                                  f16* __restrict__ ph, f16* __restrict__ pm)
{
    const long long t = (long long)blockIdx.x * blockDim.x + threadIdx.x;
    const long long total = (long long)MROWS * SEQC / 8;
    if (t >= total) return;
    const long long e = t * 8;
    const int mr = (int)(e / SEQC);
    const int c0 = (int)(e % SEQC);
    const int src = (c0 < 2560) ? c0 : c0 + 4;
    const float4 v0 = *(const float4*)(seq + (size_t)mr * 3076 + src);
    const float4 v1 = *(const float4*)(seq + (size_t)mr * 3076 + src + 4);
    const float v[8] = {v0.x, v0.y, v0.z, v0.w, v1.x, v1.y, v1.z, v1.w};
    f16 h[8], m[8];
#pragma unroll
    for (int i = 0; i < 8; i++) f16_split2(v[i], h[i], m[i]);
    const size_t d = (size_t)mr * SEQC + c0;
    *(uint4*)(ph + d) = *(uint4*)h;
    *(uint4*)(pm + d) = *(uint4*)m;
}

// fused split of all 6 weight matrices (one launch, descriptor table by value)
struct WSplitArgs {
    const float* src[6];
    int N[6], K[6], Kp[6];
    int off[6];      // element offset into the padded plane
    int cum[7];      // cumulative padded element counts
};
__global__ void split_w_all_kernel(WSplitArgs a,
                                   f16* __restrict__ ph, f16* __restrict__ pm)
{
    const int i = blockIdx.x * blockDim.x + threadIdx.x;
    if (i >= a.cum[6]) return;
    int s = 0;
#pragma unroll
    for (int j = 1; j < 6; ++j) s += (i >= a.cum[j]);
    const int li = i - a.cum[s];
    const int n = li / a.Kp[s], k = li % a.Kp[s];
    const float v = (k < a.K[s]) ? a.src[s][(size_t)n * a.K[s] + k] : 0.0f;
    f16 h, m;
    f16_split2(v, h, m);
    const size_t d = (size_t)a.off[s] + li;
    ph[d] = h; pm[d] = m;
}

__global__ void pos_pad2_kernel(const float* __restrict__ seq,
                                f16* __restrict__ ph, f16* __restrict__ pm)
{
    const int i = blockIdx.x * blockDim.x + threadIdx.x;
    if (i >= MROWS * 64) return;
    const int mr = i >> 6, j = i & 63;
    float v = 0.0f;
    int col;
    if (j < 4) { v = fmaxf(seq[(size_t)mr * 3076 + 2560 + j], 0.0f); col = 256 + j; }
    else       { col = 384 + j; }
    f16 h, m;
    f16_split2(v, h, m);
    const size_t d = (size_t)mr * 448 + col;
    ph[d] = h; pm[d] = m;
}

// ---------------- Sinkhorn ----------------
__global__ __launch_bounds__(512) void sinkhorn_kernel(
    const float* __restrict__ logits, float* __restrict__ out)
{
    __shared__ float X[36][37];
    __shared__ float red[36];
    const int b = blockIdx.x;
    const int t = threadIdx.x;
    const float* src = logits + (size_t)b * 1296;

    for (int i = t; i < 1296; i += 512)
        X[i / 36][i % 36] = expf(src[i] * TAU_INV);
    __syncthreads();

    for (int it = 0; it < 20; ++it) {
        if (t < 36) {
            float mx = -INFINITY;
#pragma unroll
            for (int c = 0; c < 36; c++) mx = fmaxf(mx, X[t][c]);
            float s = 0.0f;
#pragma unroll
            for (int c = 0; c < 36; c++) s += expf(X[t][c] - mx);
            red[t] = mx + logf(s);
        }
        __syncthreads();
        for (int i = t; i < 1296; i += 512) X[i / 36][i % 36] -= red[i / 36];
        __syncthreads();
        if (t < 36) {
            float mx = -INFINITY;
#pragma unroll
            for (int r = 0; r < 36; r++) mx = fmaxf(mx, X[r][t]);
            float s = 0.0f;
#pragma unroll
            for (int r = 0; r < 36; r++) s += expf(X[r][t] - mx);
            red[t] = mx + logf(s);
        }
        __syncthreads();
        for (int i = t; i < 1296; i += 512) X[i / 36][i % 36] -= red[i % 36];
        __syncthreads();
    }
    for (int i = t; i < 1296; i += 512)
        out[(size_t)b * 1296 + i] = expf(X[i / 36][i % 36]);
}

// ---------------- host ----------------
extern "C" void kernel_launch(void* const* d_in, const int* in_sizes, int n_in,
                              void* d_out, int out_size)
{
    const float* seq   = (const float*)d_in[0];
    const float* W1t_w = (const float*)d_in[1];
    const float* W1t_b = (const float*)d_in[2];
    const float* W1v_w = (const float*)d_in[3];
    const float* W1v_b = (const float*)d_in[4];
    const float* W2v_w = (const float*)d_in[5];
    const float* W2v_b = (const float*)d_in[6];
    const float* W1s_w = (const float*)d_in[7];
    const float* W1s_b = (const float*)d_in[8];
    const float* Wfp_w = (const float*)d_in[9];
    const float* Wfp_b = (const float*)d_in[10];
    const float* Wfc_w = (const float*)d_in[11];
    const float* Wfc_b = (const float*)d_in[12];
    float* out = (float*)d_out;

    f16 *sq[2], *xv[2], *cc[2], *a3[2], *wp[2];
    float* logits;
    {
        f16* p;
        cudaGetSymbolAddress((void**)&p, g_seqP);
        sq[0] = p; sq[1] = p + (size_t)MROWS * SEQC;
        cudaGetSymbolAddress((void**)&p, g_xvP);
        xv[0] = p; xv[1] = p + (size_t)MROWS * 512;
        cudaGetSymbolAddress((void**)&p, g_ccP);
        cc[0] = p; cc[1] = p + (size_t)MROWS * 448;
        cudaGetSymbolAddress((void**)&p, g_a3P);
        a3[0] = p; a3[1] = p + (size_t)MROWS * 256;
        cudaGetSymbolAddress((void**)&p, g_wP);
        const size_t wsz = 128*512 + 512*2048 + 128*512 + 128*512 + 256*448 + 36*256;
        wp[0] = p; wp[1] = p + wsz;
        cudaGetSymbolAddress((void**)&logits, g_logits);
    }

    cudaFuncSetAttribute(gemm_f16e<0>, cudaFuncAttributeMaxDynamicSharedMemorySize, GEMM_SMEM);
    cudaFuncSetAttribute(gemm_f16e<1>, cudaFuncAttributeMaxDynamicSharedMemorySize, GEMM_SMEM);

    // side stream + events (created per call; graph capture propagates through
    // the event fork/join; never destroyed while capture is active)
    cudaStream_t s1;
    cudaStreamCreateWithFlags(&s1, cudaStreamNonBlocking);
    cudaEvent_t e_fork, e_w, e_seq, e_join;
    cudaEventCreateWithFlags(&e_fork, cudaEventDisableTiming);
    cudaEventCreateWithFlags(&e_w,    cudaEventDisableTiming);
    cudaEventCreateWithFlags(&e_seq,  cudaEventDisableTiming);
    cudaEventCreateWithFlags(&e_join, cudaEventDisableTiming);

    // ---- fork ----
    cudaEventRecord(e_fork, 0);
    cudaStreamWaitEvent(s1, e_fork, 0);

    // side stream: weight splits + pos/pad
    {
        WSplitArgs a;
        const float* srcs[6] = {W1t_w, W1v_w, W2v_w, W1s_w, Wfp_w, Wfc_w};
        const int Ns[6]  = {128, 512, 128, 128, 256, 36};
        const int Ks[6]  = {512, 2048, 512, 512, 388, 256};
        const int Kps[6] = {512, 2048, 512, 512, 448, 256};
        const int offs[6] = {WOFF_TXT, WOFF_VIS1, WOFF_VIS2, WOFF_SEN, WOFF_FCP, WOFF_FC};
        int c = 0;
        for (int j = 0; j < 6; ++j) {
            a.src[j] = srcs[j]; a.N[j] = Ns[j]; a.K[j] = Ks[j]; a.Kp[j] = Kps[j];
            a.off[j] = offs[j]; a.cum[j] = c; c += Ns[j] * Kps[j];
        }
        a.cum[6] = c;
        split_w_all_kernel<<<(c + 255) / 256, 256, 0, s1>>>(a, wp[0], wp[1]);
    }
    cudaEventRecord(e_w, s1);
    pos_pad2_kernel<<<(MROWS * 64 + 255) / 256, 256, 0, s1>>>(seq, cc[0], cc[1]);

    // main stream: seq split
    {
        const long long n = (long long)MROWS * SEQC / 8;
        split_seq2_kernel<<<(unsigned)((n + 255) / 256), 256>>>(seq, sq[0], sq[1]);
    }
    cudaEventRecord(e_seq, 0);
    cudaStreamWaitEvent(0, e_w, 0);       // vis1 needs weights

    const int mT = MROWS / 128;   // 144

    // main: vis1 (the big one)
    gemm_f16e<0><<<dim3(4, mT), 256, GEMM_SMEM>>>(
        sq[0] + 512, sq[1] + 512, SEQC,
        wp[0] + WOFF_VIS1, wp[1] + WOFF_VIS1, 2048, W1v_b,
        xv[0], xv[1], nullptr, 512, 512, 32);

    // side: txt + sen (need seq split + weights, overlap vis1)
    cudaStreamWaitEvent(s1, e_seq, 0);
    gemm_f16e<0><<<dim3(1, mT), 256, GEMM_SMEM, s1>>>(
        sq[0], sq[1], SEQC,
        wp[0] + WOFF_TXT, wp[1] + WOFF_TXT, 512, W1t_b,
        cc[0], cc[1], nullptr, 448, 128, 8);
    gemm_f16e<0><<<dim3(1, mT), 256, GEMM_SMEM, s1>>>(
        sq[0] + 2560, sq[1] + 2560, SEQC,
        wp[0] + WOFF_SEN, wp[1] + WOFF_SEN, 512, W1s_b,
        cc[0] + 260, cc[1] + 260, nullptr, 448, 128, 8);
    cudaEventRecord(e_join, s1);
    cudaStreamWaitEvent(0, e_join, 0);

    // main: vis2 -> fcp -> fc -> sinkhorn
    gemm_f16e<0><<<dim3(1, mT), 256, GEMM_SMEM>>>(
        xv[0], xv[1], 512,
        wp[0] + WOFF_VIS2, wp[1] + WOFF_VIS2, 512, W2v_b,
        cc[0] + 128, cc[1] + 128, nullptr, 448, 128, 8);
    gemm_f16e<0><<<dim3(2, mT), 256, GEMM_SMEM>>>(
        cc[0], cc[1], 448,
        wp[0] + WOFF_FCP, wp[1] + WOFF_FCP, 448, Wfp_b,
        a3[0], a3[1], nullptr, 256, 256, 7);
    gemm_f16e<1><<<dim3(1, mT), 256, GEMM_SMEM>>>(
        a3[0], a3[1], 256,
        wp[0] + WOFF_FC, wp[1] + WOFF_FC, 256, Wfc_b,
        nullptr, nullptr, logits, 36, 36, 4);

    sinkhorn_kernel<<<512, 512>>>(logits, out);
}

// round 15
// speedup vs baseline: 3.6332x; 1.0043x over previous
#include <cuda_runtime.h>
#include <cuda_fp16.h>
#include <math.h>
#include <stdint.h>

#define MROWS 18432
#define TAU_INV 20.0f
#define MSCALE 4096.0f
#define INV_MSCALE (1.0f / 4096.0f)

typedef __half f16;

// ---------------- scratch (device globals; alloc-free) ----------------
#define SEQC 3072
__device__ __align__(128) f16 g_seqP[2][(size_t)MROWS * SEQC];
__device__ __align__(128) f16 g_xvP [2][(size_t)MROWS * 512];
__device__ __align__(128) f16 g_ccP [2][(size_t)MROWS * 448];
__device__ __align__(128) f16 g_a3P [2][(size_t)MROWS * 256];
__device__ __align__(128) f16 g_wP  [2][128*512 + 512*2048 + 128*512 + 128*512 + 256*448 + 36*256];
__device__ __align__(128) float g_logits[(size_t)MROWS * 36];

#define WOFF_TXT   0
#define WOFF_VIS1  (WOFF_TXT  + 128*512)
#define WOFF_VIS2  (WOFF_VIS1 + 512*2048)
#define WOFF_SEN   (WOFF_VIS2 + 128*512)
#define WOFF_FCP   (WOFF_SEN  + 128*512)
#define WOFF_FC    (WOFF_FCP  + 256*448)

// ---------------- smem layout ----------------
#define ROWB    144
#define A_PLANE (128 * ROWB)
#define W_PLANE (128 * ROWB)
#define W_OFF   (2 * A_PLANE)
#define STAGE_B (2 * A_PLANE + 2 * W_PLANE)   // 73728
#define NSTG    3
#define GEMM_SMEM (NSTG * STAGE_B)            // 221184

// ---------------- PTX helpers ----------------
__device__ __forceinline__ uint32_t smem_u32(const void* p) {
    uint32_t a;
    asm("{ .reg .u64 t; cvta.to.shared.u64 t, %1; cvt.u32.u64 %0, t; }" : "=r"(a) : "l"(p));
    return a;
}

#define CPA(dst, src, pb) \
    asm volatile("cp.async.cg.shared.global [%0], [%1], 16, %2;" \
                 :: "r"(dst), "l"(src), "r"(pb) : "memory")
#define CPA_COMMIT() asm volatile("cp.async.commit_group;" ::: "memory")
#define CPA_WAIT1()  asm volatile("cp.async.wait_group 1;" ::: "memory")

#define LDSM4(r0, r1, r2, r3, a) \
    asm volatile("ldmatrix.sync.aligned.m8n8.x4.shared.b16 {%0,%1,%2,%3}, [%4];" \
                 : "=r"(r0), "=r"(r1), "=r"(r2), "=r"(r3) : "r"(a))

#define MMAH(d, a, b) \
    asm volatile("mma.sync.aligned.m16n8k16.row.col.f32.f16.f16.f32 " \
                 "{%0,%1,%2,%3}, {%4,%5,%6,%7}, {%8,%9}, {%0,%1,%2,%3};" \
                 : "+f"((d)[0]), "+f"((d)[1]), "+f"((d)[2]), "+f"((d)[3]) \
                 : "r"((a)[0]), "r"((a)[1]), "r"((a)[2]), "r"((a)[3]), \
                   "r"((b)[0]), "r"((b)[1]))

__device__ __forceinline__ void f16_split2(float v, f16& h, f16& m) {
    h = __float2half_rn(v);
    m = __float2half_rn((v - __half2float(h)) * MSCALE);
}

// ---------------- GEMM body ----------------
// Single barrier per chunk: wait_group 1 -> barrier -> issue load(t+2) -> MMA(t).
template <int OUTMODE>
__device__ __forceinline__ void gemm_body(
    const f16* __restrict__ Ah, const f16* __restrict__ Am, int lda,
    const f16* __restrict__ Wh, const f16* __restrict__ Wm, int ldw,
    const float* __restrict__ bias,
    f16* __restrict__ Ch, f16* __restrict__ Cm, float* __restrict__ Cf,
    int ldc, int N, int nchunks, int bm, int bn, uint32_t sb)
{
    const int tid  = threadIdx.x;
    const int wid  = tid >> 5;
    const int lane = tid & 31;
    const int g    = lane >> 2;
    const int tg   = lane & 3;
    const int wm   = wid & 1;
    const int wn   = wid >> 1;

    float accm[4][4][4], accs[4][4][4];
#pragma unroll
    for (int i = 0; i < 4; i++)
#pragma unroll
        for (int j = 0; j < 4; j++)
#pragma unroll
            for (int e = 0; e < 4; e++) { accm[i][j][e] = 0.0f; accs[i][j][e] = 0.0f; }

    auto load_stage = [&](int buf, int k0) {
        const uint32_t st = sb + buf * STAGE_B;
#pragma unroll
        for (int j = 0; j < 4; ++j) {
            const int e   = tid + 256 * j;
            const int row = e >> 3;
            const int ch  = e & 7;
            const uint32_t d = st + row * ROWB + ch * 16;
            const size_t srcA = (size_t)(bm + row) * lda + k0 + ch * 8;
            CPA(d,           (const void*)(Ah + srcA), 16);
            CPA(d + A_PLANE, (const void*)(Am + srcA), 16);
            const int n  = bn + row;
            const int pb = (n < N) ? 16 : 0;
            const size_t srcW = (size_t)((n < N) ? n : 0) * ldw + k0 + ch * 8;
            const uint32_t dw = st + W_OFF + row * ROWB + ch * 16;
            CPA(dw,           (const void*)(Wh + srcW), pb);
            CPA(dw + W_PLANE, (const void*)(Wm + srcW), pb);
        }
        CPA_COMMIT();
    };

    const int nT = nchunks;
    load_stage(0, 0);
    if (nT > 1) load_stage(1, 64); else CPA_COMMIT();

    const uint32_t a_off = (uint32_t)((wm * 64 + (lane & 15)) * ROWB + (lane >> 4) * 16);
    const int b_row = ((lane >> 4) & 1) * 8 + (lane & 7);
    const int b_ch  = (lane >> 3) & 1;
    const uint32_t b_off = (uint32_t)(W_OFF + (wn * 32 + b_row) * ROWB + b_ch * 16);

    for (int t = 0; t < nT; ++t) {
        CPA_WAIT1();            // stage t resident (one commit per iteration)
        __syncthreads();        // all warps done reading buffer (t+2)%3 == (t-1)%3
        if (t + 2 < nT) load_stage((t + 2) % NSTG, (t + 2) * 64);
        else            CPA_COMMIT();

        const uint32_t st = sb + (t % NSTG) * STAGE_B;
#pragma unroll
        for (int ks = 0; ks < 4; ++ks) {
            const uint32_t ko = ks * 32;
            uint32_t ah[4][4], am[4][4];
            uint32_t bh[4][2], bm_[4][2];
            const uint32_t ab = st + a_off + ko;
#pragma unroll
            for (int mt = 0; mt < 4; ++mt) {
                const uint32_t r = ab + mt * (16 * ROWB);
                LDSM4(ah[mt][0], ah[mt][1], ah[mt][2], ah[mt][3], r);
                LDSM4(am[mt][0], am[mt][1], am[mt][2], am[mt][3], r + A_PLANE);
            }
            const uint32_t bb = st + b_off + ko;
#pragma unroll
            for (int p = 0; p < 2; ++p) {
                const uint32_t r = bb + p * (16 * ROWB);
                LDSM4(bh[2*p][0],  bh[2*p][1],  bh[2*p+1][0],  bh[2*p+1][1],  r);
                LDSM4(bm_[2*p][0], bm_[2*p][1], bm_[2*p+1][0], bm_[2*p+1][1], r + W_PLANE);
            }
#pragma unroll
            for (int mt = 0; mt < 4; ++mt)
#pragma unroll
                for (int nt = 0; nt < 4; ++nt) {
                    MMAH(accm[mt][nt], ah[mt], bh[nt]);
                    MMAH(accs[mt][nt], ah[mt], bm_[nt]);
                    MMAH(accs[mt][nt], am[mt], bh[nt]);
                }
        }
    }

#pragma unroll
    for (int nt = 0; nt < 4; ++nt) {
        const int cg = bn + wn * 32 + nt * 8 + tg * 2;
#pragma unroll
        for (int mt = 0; mt < 4; ++mt) {
            const int r0 = bm + wm * 64 + mt * 16 + g;
#pragma unroll
            for (int h = 0; h < 2; ++h) {
                const int r = r0 + h * 8;
                float v0 = fmaf(accs[mt][nt][2*h+0], INV_MSCALE, accm[mt][nt][2*h+0]);
                float v1 = fmaf(accs[mt][nt][2*h+1], INV_MSCALE, accm[mt][nt][2*h+1]);
                if (OUTMODE == 0) {
                    v0 = fmaxf(v0 + bias[cg],     0.0f);
                    v1 = fmaxf(v1 + bias[cg + 1], 0.0f);
                    f16 h0, m0, h1, m1;
                    f16_split2(v0, h0, m0);
                    f16_split2(v1, h1, m1);
                    const size_t gdx = (size_t)r * ldc + cg;
                    __half2 p;
                    p.x = h0; p.y = h1; *(uint32_t*)(Ch + gdx) = *(uint32_t*)&p;
                    p.x = m0; p.y = m1; *(uint32_t*)(Cm + gdx) = *(uint32_t*)&p;
                } else {
                    if (cg < N)     Cf[(size_t)r * ldc + cg]     = tanhf(v0 + bias[cg]);
                    if (cg + 1 < N) Cf[(size_t)r * ldc + cg + 1] = tanhf(v1 + bias[cg + 1]);
                }
            }
        }
    }
}

template <int OUTMODE>
__global__ __launch_bounds__(256, 1) void gemm_f16e(
    const f16* __restrict__ Ah, const f16* __restrict__ Am, int lda,
    const f16* __restrict__ Wh, const f16* __restrict__ Wm, int ldw,
    const float* __restrict__ bias,
    f16* __restrict__ Ch, f16* __restrict__ Cm, float* __restrict__ Cf,
    int ldc, int N, int nchunks)
{
    extern __shared__ char smem[];
    gemm_body<OUTMODE>(Ah, Am, lda, Wh, Wm, ldw, bias, Ch, Cm, Cf,
                       ldc, N, nchunks, blockIdx.y * 128, blockIdx.x * 128,
                       smem_u32(smem));
}

// txt + sen in one launch (z selects), both N=128, K=512, out into cc planes
__global__ __launch_bounds__(256, 1) void gemm_f16e_dual(
    const f16* __restrict__ sq0, const f16* __restrict__ sq1,
    const f16* __restrict__ wt0, const f16* __restrict__ wt1,
    const f16* __restrict__ ws0, const f16* __restrict__ ws1,
    const float* __restrict__ bt, const float* __restrict__ bs,
    f16* __restrict__ cc0, f16* __restrict__ cc1)
{
    extern __shared__ char smem[];
    const int z = blockIdx.z;
    const f16* Ah = z ? sq0 + 2560 : sq0;
    const f16* Am = z ? sq1 + 2560 : sq1;
    const f16* Wh = z ? ws0 : wt0;
    const f16* Wm = z ? ws1 : wt1;
    const float* b = z ? bs : bt;
    f16* Ch = z ? cc0 + 260 : cc0;
    f16* Cm = z ? cc1 + 260 : cc1;
    gemm_body<0>(Ah, Am, SEQC, Wh, Wm, 512, b, Ch, Cm, nullptr,
                 448, 128, 8, blockIdx.y * 128, 0, smem_u32(smem));
}

// ---------------- pre-split kernels ----------------
__global__ void split_seq2_kernel(const float* __restrict__ seq,
                                  f16* __restrict__ ph, f16* __restrict__ pm)
{
    const long long t = (long long)blockIdx.x * blockDim.x + threadIdx.x;
    const long long total = (long long)MROWS * SEQC / 8;
    if (t >= total) return;
    const long long e = t * 8;
    const int mr = (int)(e / SEQC);
    const int c0 = (int)(e % SEQC);
    const int src = (c0 < 2560) ? c0 : c0 + 4;
    const float4 v0 = *(const float4*)(seq + (size_t)mr * 3076 + src);
    const float4 v1 = *(const float4*)(seq + (size_t)mr * 3076 + src + 4);
    const float v[8] = {v0.x, v0.y, v0.z, v0.w, v1.x, v1.y, v1.z, v1.w};
    f16 h[8], m[8];
#pragma unroll
    for (int i = 0; i < 8; i++) f16_split2(v[i], h[i], m[i]);
    const size_t d = (size_t)mr * SEQC + c0;
    *(uint4*)(ph + d) = *(uint4*)h;
    *(uint4*)(pm + d) = *(uint4*)m;
}

struct WSplitArgs {
    const float* src[6];
    int N[6], K[6], Kp[6];
    int off[6];
    int cum[7];
};
__global__ void split_w_all_kernel(WSplitArgs a,
                                   f16* __restrict__ ph, f16* __restrict__ pm)
{
    const int i = blockIdx.x * blockDim.x + threadIdx.x;
    if (i >= a.cum[6]) return;
    int s = 0;
#pragma unroll
    for (int j = 1; j < 6; ++j) s += (i >= a.cum[j]);
    const int li = i - a.cum[s];
    const int n = li / a.Kp[s], k = li % a.Kp[s];
    const float v = (k < a.K[s]) ? a.src[s][(size_t)n * a.K[s] + k] : 0.0f;
    f16 h, m;
    f16_split2(v, h, m);
    const size_t d = (size_t)a.off[s] + li;
    ph[d] = h; pm[d] = m;
}

__global__ void pos_pad2_kernel(const float* __restrict__ seq,
                                f16* __restrict__ ph, f16* __restrict__ pm)
{
    const int i = blockIdx.x * blockDim.x + threadIdx.x;
    if (i >= MROWS * 64) return;
    const int mr = i >> 6, j = i & 63;
    float v = 0.0f;
    int col;
    if (j < 4) { v = fmaxf(seq[(size_t)mr * 3076 + 2560 + j], 0.0f); col = 256 + j; }
    else       { col = 384 + j; }
    f16 h, m;
    f16_split2(v, h, m);
    const size_t d = (size_t)mr * 448 + col;
    ph[d] = h; pm[d] = m;
}

// ---------------- Sinkhorn ----------------
__global__ __launch_bounds__(512) void sinkhorn_kernel(
    const float* __restrict__ logits, float* __restrict__ out)
{
    __shared__ float X[36][37];
    __shared__ float red[36];
    const int b = blockIdx.x;
    const int t = threadIdx.x;
    const float* src = logits + (size_t)b * 1296;

    for (int i = t; i < 1296; i += 512)
        X[i / 36][i % 36] = expf(src[i] * TAU_INV);
    __syncthreads();

    for (int it = 0; it < 20; ++it) {
        if (t < 36) {
            float mx = -INFINITY;
#pragma unroll
            for (int c = 0; c < 36; c++) mx = fmaxf(mx, X[t][c]);
            float s = 0.0f;
#pragma unroll
            for (int c = 0; c < 36; c++) s += expf(X[t][c] - mx);
            red[t] = mx + logf(s);
        }
        __syncthreads();
        for (int i = t; i < 1296; i += 512) X[i / 36][i % 36] -= red[i / 36];
        __syncthreads();
        if (t < 36) {
            float mx = -INFINITY;
#pragma unroll
            for (int r = 0; r < 36; r++) mx = fmaxf(mx, X[r][t]);
            float s = 0.0f;
#pragma unroll
            for (int r = 0; r < 36; r++) s += expf(X[r][t] - mx);
            red[t] = mx + logf(s);
        }
        __syncthreads();
        for (int i = t; i < 1296; i += 512) X[i / 36][i % 36] -= red[i % 36];
        __syncthreads();
    }
    for (int i = t; i < 1296; i += 512)
        out[(size_t)b * 1296 + i] = expf(X[i / 36][i % 36]);
}

// ---------------- host ----------------
extern "C" void kernel_launch(void* const* d_in, const int* in_sizes, int n_in,
                              void* d_out, int out_size)
{
    const float* seq   = (const float*)d_in[0];
    const float* W1t_w = (const float*)d_in[1];
    const float* W1t_b = (const float*)d_in[2];
    const float* W1v_w = (const float*)d_in[3];
    const float* W1v_b = (const float*)d_in[4];
    const float* W2v_w = (const float*)d_in[5];
    const float* W2v_b = (const float*)d_in[6];
    const float* W1s_w = (const float*)d_in[7];
    const float* W1s_b = (const float*)d_in[8];
    const float* Wfp_w = (const float*)d_in[9];
    const float* Wfp_b = (const float*)d_in[10];
    const float* Wfc_w = (const float*)d_in[11];
    const float* Wfc_b = (const float*)d_in[12];
    float* out = (float*)d_out;

    f16 *sq[2], *xv[2], *cc[2], *a3[2], *wp[2];
    float* logits;
    {
        f16* p;
        cudaGetSymbolAddress((void**)&p, g_seqP);
        sq[0] = p; sq[1] = p + (size_t)MROWS * SEQC;
        cudaGetSymbolAddress((void**)&p, g_xvP);
        xv[0] = p; xv[1] = p + (size_t)MROWS * 512;
        cudaGetSymbolAddress((void**)&p, g_ccP);
        cc[0] = p; cc[1] = p + (size_t)MROWS * 448;
        cudaGetSymbolAddress((void**)&p, g_a3P);
        a3[0] = p; a3[1] = p + (size_t)MROWS * 256;
        cudaGetSymbolAddress((void**)&p, g_wP);
        const size_t wsz = 128*512 + 512*2048 + 128*512 + 128*512 + 256*448 + 36*256;
        wp[0] = p; wp[1] = p + wsz;
        cudaGetSymbolAddress((void**)&logits, g_logits);
    }

    cudaFuncSetAttribute(gemm_f16e<0>, cudaFuncAttributeMaxDynamicSharedMemorySize, GEMM_SMEM);
    cudaFuncSetAttribute(gemm_f16e<1>, cudaFuncAttributeMaxDynamicSharedMemorySize, GEMM_SMEM);
    cudaFuncSetAttribute(gemm_f16e_dual, cudaFuncAttributeMaxDynamicSharedMemorySize, GEMM_SMEM);

    cudaStream_t s1;
    cudaStreamCreateWithFlags(&s1, cudaStreamNonBlocking);
    cudaEvent_t e_fork, e_w, e_seq, e_join;
    cudaEventCreateWithFlags(&e_fork, cudaEventDisableTiming);
    cudaEventCreateWithFlags(&e_w,    cudaEventDisableTiming);
    cudaEventCreateWithFlags(&e_seq,  cudaEventDisableTiming);
    cudaEventCreateWithFlags(&e_join, cudaEventDisableTiming);

    // ---- fork ----
    cudaEventRecord(e_fork, 0);
    cudaStreamWaitEvent(s1, e_fork, 0);

    // side: weight splits + pos/pad
    {
        WSplitArgs a;
        const float* srcs[6] = {W1t_w, W1v_w, W2v_w, W1s_w, Wfp_w, Wfc_w};
        const int Ns[6]  = {128, 512, 128, 128, 256, 36};
        const int Ks[6]  = {512, 2048, 512, 512, 388, 256};
        const int Kps[6] = {512, 2048, 512, 512, 448, 256};
        const int offs[6] = {WOFF_TXT, WOFF_VIS1, WOFF_VIS2, WOFF_SEN, WOFF_FCP, WOFF_FC};
        int c = 0;
        for (int j = 0; j < 6; ++j) {
            a.src[j] = srcs[j]; a.N[j] = Ns[j]; a.K[j] = Ks[j]; a.Kp[j] = Kps[j];
            a.off[j] = offs[j]; a.cum[j] = c; c += Ns[j] * Kps[j];
        }
        a.cum[6] = c;
        split_w_all_kernel<<<(c + 255) / 256, 256, 0, s1>>>(a, wp[0], wp[1]);
    }
    cudaEventRecord(e_w, s1);
    pos_pad2_kernel<<<(MROWS * 64 + 255) / 256, 256, 0, s1>>>(seq, cc[0], cc[1]);

    // main: seq split
    {
        const long long n = (long long)MROWS * SEQC / 8;
        split_seq2_kernel<<<(unsigned)((n + 255) / 256), 256>>>(seq, sq[0], sq[1]);
    }
    cudaEventRecord(e_seq, 0);
    cudaStreamWaitEvent(0, e_w, 0);

    const int mT = MROWS / 128;   // 144

    // main: vis1
    gemm_f16e<0><<<dim3(4, mT), 256, GEMM_SMEM>>>(
        sq[0] + 512, sq[1] + 512, SEQC,
        wp[0] + WOFF_VIS1, wp[1] + WOFF_VIS1, 2048, W1v_b,
        xv[0], xv[1], nullptr, 512, 512, 32);

    // side: txt + sen fused (overlap vis1)
    cudaStreamWaitEvent(s1, e_seq, 0);
    gemm_f16e_dual<<<dim3(1, mT, 2), 256, GEMM_SMEM, s1>>>(
        sq[0], sq[1],
        wp[0] + WOFF_TXT, wp[1] + WOFF_TXT,
        wp[0] + WOFF_SEN, wp[1] + WOFF_SEN,
        W1t_b, W1s_b, cc[0], cc[1]);
    cudaEventRecord(e_join, s1);
    cudaStreamWaitEvent(0, e_join, 0);

    // main: vis2 -> fcp -> fc -> sinkhorn
    gemm_f16e<0><<<dim3(1, mT), 256, GEMM_SMEM>>>(
        xv[0], xv[1], 512,
        wp[0] + WOFF_VIS2, wp[1] + WOFF_VIS2, 512, W2v_b,
        cc[0] + 128, cc[1] + 128, nullptr, 448, 128, 8);
    gemm_f16e<0><<<dim3(2, mT), 256, GEMM_SMEM>>>(
        cc[0], cc[1], 448,
        wp[0] + WOFF_FCP, wp[1] + WOFF_FCP, 448, Wfp_b,
        a3[0], a3[1], nullptr, 256, 256, 7);
    gemm_f16e<1><<<dim3(1, mT), 256, GEMM_SMEM>>>(
        a3[0], a3[1], 256,
        wp[0] + WOFF_FC, wp[1] + WOFF_FC, 256, Wfc_b,
        nullptr, nullptr, logits, 36, 36, 4);

    sinkhorn_kernel<<<512, 512>>>(logits, out);
}

// round 16
// speedup vs baseline: 3.6906x; 1.0158x over previous
#include <cuda_runtime.h>
#include <cuda_fp16.h>
#include <math.h>
#include <stdint.h>

#define MROWS 18432
#define TAU_INV 20.0f
#define MSCALE 4096.0f
#define INV_MSCALE (1.0f / 4096.0f)

typedef __half f16;

// ---------------- scratch (device globals; alloc-free) ----------------
#define SEQC 3072
__device__ __align__(128) f16 g_seqP[2][(size_t)MROWS * SEQC];
__device__ __align__(128) f16 g_xvP [2][(size_t)MROWS * 512];
__device__ __align__(128) f16 g_ccP [2][(size_t)MROWS * 448];
__device__ __align__(128) f16 g_a3P [2][(size_t)MROWS * 256];
__device__ __align__(128) f16 g_wP  [2][128*512 + 512*2048 + 128*512 + 128*512 + 256*448 + 36*256];
__device__ __align__(128) float g_logits[(size_t)MROWS * 36];

#define WOFF_TXT   0
#define WOFF_VIS1  (WOFF_TXT  + 128*512)
#define WOFF_VIS2  (WOFF_VIS1 + 512*2048)
#define WOFF_SEN   (WOFF_VIS2 + 128*512)
#define WOFF_FCP   (WOFF_SEN  + 128*512)
#define WOFF_FC    (WOFF_FCP  + 256*448)

// ---------------- smem layout ----------------
#define ROWB    144
#define A_PLANE (128 * ROWB)
#define W_PLANE (128 * ROWB)
#define W_OFF   (2 * A_PLANE)
#define STAGE_B (2 * A_PLANE + 2 * W_PLANE)   // 73728
#define NSTG    3
#define GEMM_SMEM (NSTG * STAGE_B)            // 221184

// ---------------- PTX helpers ----------------
__device__ __forceinline__ uint32_t smem_u32(const void* p) {
    uint32_t a;
    asm("{ .reg .u64 t; cvta.to.shared.u64 t, %1; cvt.u32.u64 %0, t; }" : "=r"(a) : "l"(p));
    return a;
}

#define CPA(dst, src, pb) \
    asm volatile("cp.async.cg.shared.global [%0], [%1], 16, %2;" \
                 :: "r"(dst), "l"(src), "r"(pb) : "memory")
#define CPA_COMMIT() asm volatile("cp.async.commit_group;" ::: "memory")
#define CPA_WAIT1()  asm volatile("cp.async.wait_group 1;" ::: "memory")

#define LDSM4(r0, r1, r2, r3, a) \
    asm volatile("ldmatrix.sync.aligned.m8n8.x4.shared.b16 {%0,%1,%2,%3}, [%4];" \
                 : "=r"(r0), "=r"(r1), "=r"(r2), "=r"(r3) : "r"(a))

#define MMAH(d, a, b) \
    asm volatile("mma.sync.aligned.m16n8k16.row.col.f32.f16.f16.f32 " \
                 "{%0,%1,%2,%3}, {%4,%5,%6,%7}, {%8,%9}, {%0,%1,%2,%3};" \
                 : "+f"((d)[0]), "+f"((d)[1]), "+f"((d)[2]), "+f"((d)[3]) \
                 : "r"((a)[0]), "r"((a)[1]), "r"((a)[2]), "r"((a)[3]), \
                   "r"((b)[0]), "r"((b)[1]))

__device__ __forceinline__ void f16_split2(float v, f16& h, f16& m) {
    h = __float2half_rn(v);
    m = __float2half_rn((v - __half2float(h)) * MSCALE);
}

// ---------------- GEMM body ----------------
// 512 threads, 16 warps (4 m x 4 n), warp tile 32x32 -> 4 warps/SMSP.
template <int OUTMODE>
__device__ __forceinline__ void gemm_body(
    const f16* __restrict__ Ah, const f16* __restrict__ Am, int lda,
    const f16* __restrict__ Wh, const f16* __restrict__ Wm, int ldw,
    const float* __restrict__ bias,
    f16* __restrict__ Ch, f16* __restrict__ Cm, float* __restrict__ Cf,
    int ldc, int N, int nchunks, int bm, int bn, uint32_t sb)
{
    const int tid  = threadIdx.x;
    const int wid  = tid >> 5;
    const int lane = tid & 31;
    const int g    = lane >> 2;
    const int tg   = lane & 3;
    const int wm   = wid & 3;        // 4 row-blocks of 32
    const int wn   = wid >> 2;       // 4 col-blocks of 32

    float accm[2][4][4], accs[2][4][4];
#pragma unroll
    for (int i = 0; i < 2; i++)
#pragma unroll
        for (int j = 0; j < 4; j++)
#pragma unroll
            for (int e = 0; e < 4; e++) { accm[i][j][e] = 0.0f; accs[i][j][e] = 0.0f; }

    auto load_stage = [&](int buf, int k0) {
        const uint32_t st = sb + buf * STAGE_B;
#pragma unroll
        for (int j = 0; j < 2; ++j) {
            const int e   = tid + 512 * j;     // 0..1023
            const int row = e >> 3;            // 0..127
            const int ch  = e & 7;
            const uint32_t d = st + row * ROWB + ch * 16;
            const size_t srcA = (size_t)(bm + row) * lda + k0 + ch * 8;
            CPA(d,           (const void*)(Ah + srcA), 16);
            CPA(d + A_PLANE, (const void*)(Am + srcA), 16);
            const int n  = bn + row;
            const int pb = (n < N) ? 16 : 0;
            const size_t srcW = (size_t)((n < N) ? n : 0) * ldw + k0 + ch * 8;
            const uint32_t dw = st + W_OFF + row * ROWB + ch * 16;
            CPA(dw,           (const void*)(Wh + srcW), pb);
            CPA(dw + W_PLANE, (const void*)(Wm + srcW), pb);
        }
        CPA_COMMIT();
    };

    const int nT = nchunks;
    load_stage(0, 0);
    if (nT > 1) load_stage(1, 64); else CPA_COMMIT();

    const uint32_t a_off = (uint32_t)((wm * 32 + (lane & 15)) * ROWB + (lane >> 4) * 16);
    const int b_row = ((lane >> 4) & 1) * 8 + (lane & 7);
    const int b_ch  = (lane >> 3) & 1;
    const uint32_t b_off = (uint32_t)(W_OFF + (wn * 32 + b_row) * ROWB + b_ch * 16);

    for (int t = 0; t < nT; ++t) {
        CPA_WAIT1();
        __syncthreads();
        if (t + 2 < nT) load_stage((t + 2) % NSTG, (t + 2) * 64);
        else            CPA_COMMIT();

        const uint32_t st = sb + (t % NSTG) * STAGE_B;
#pragma unroll
        for (int ks = 0; ks < 4; ++ks) {
            const uint32_t ko = ks * 32;
            uint32_t ah[2][4], am[2][4];
            uint32_t bh[4][2], bm_[4][2];
            const uint32_t ab = st + a_off + ko;
#pragma unroll
            for (int mt = 0; mt < 2; ++mt) {
                const uint32_t r = ab + mt * (16 * ROWB);
                LDSM4(ah[mt][0], ah[mt][1], ah[mt][2], ah[mt][3], r);
                LDSM4(am[mt][0], am[mt][1], am[mt][2], am[mt][3], r + A_PLANE);
            }
            const uint32_t bb = st + b_off + ko;
#pragma unroll
            for (int p = 0; p < 2; ++p) {
                const uint32_t r = bb + p * (16 * ROWB);
                LDSM4(bh[2*p][0],  bh[2*p][1],  bh[2*p+1][0],  bh[2*p+1][1],  r);
                LDSM4(bm_[2*p][0], bm_[2*p][1], bm_[2*p+1][0], bm_[2*p+1][1], r + W_PLANE);
            }
#pragma unroll
            for (int mt = 0; mt < 2; ++mt)
#pragma unroll
                for (int nt = 0; nt < 4; ++nt) {
                    MMAH(accm[mt][nt], ah[mt], bh[nt]);
                    MMAH(accs[mt][nt], ah[mt], bm_[nt]);
                    MMAH(accs[mt][nt], am[mt], bh[nt]);
                }
        }
    }

#pragma unroll
    for (int nt = 0; nt < 4; ++nt) {
        const int cg = bn + wn * 32 + nt * 8 + tg * 2;
#pragma unroll
        for (int mt = 0; mt < 2; ++mt) {
            const int r0 = bm + wm * 32 + mt * 16 + g;
#pragma unroll
            for (int h = 0; h < 2; ++h) {
                const int r = r0 + h * 8;
                float v0 = fmaf(accs[mt][nt][2*h+0], INV_MSCALE, accm[mt][nt][2*h+0]);
                float v1 = fmaf(accs[mt][nt][2*h+1], INV_MSCALE, accm[mt][nt][2*h+1]);
                if (OUTMODE == 0) {
                    v0 = fmaxf(v0 + bias[cg],     0.0f);
                    v1 = fmaxf(v1 + bias[cg + 1], 0.0f);
                    f16 h0, m0, h1, m1;
                    f16_split2(v0, h0, m0);
                    f16_split2(v1, h1, m1);
                    const size_t gdx = (size_t)r * ldc + cg;
                    __half2 p;
                    p.x = h0; p.y = h1; *(uint32_t*)(Ch + gdx) = *(uint32_t*)&p;
                    p.x = m0; p.y = m1; *(uint32_t*)(Cm + gdx) = *(uint32_t*)&p;
                } else {
                    if (cg < N)     Cf[(size_t)r * ldc + cg]     = tanhf(v0 + bias[cg]);
                    if (cg + 1 < N) Cf[(size_t)r * ldc + cg + 1] = tanhf(v1 + bias[cg + 1]);
                }
            }
        }
    }
}

template <int OUTMODE>
__global__ __launch_bounds__(512, 1) void gemm_f16e(
    const f16* __restrict__ Ah, const f16* __restrict__ Am, int lda,
    const f16* __restrict__ Wh, const f16* __restrict__ Wm, int ldw,
    const float* __restrict__ bias,
    f16* __restrict__ Ch, f16* __restrict__ Cm, float* __restrict__ Cf,
    int ldc, int N, int nchunks)
{
    extern __shared__ char smem[];
    gemm_body<OUTMODE>(Ah, Am, lda, Wh, Wm, ldw, bias, Ch, Cm, Cf,
                       ldc, N, nchunks, blockIdx.y * 128, blockIdx.x * 128,
                       smem_u32(smem));
}

// txt + sen in one launch (z selects)
__global__ __launch_bounds__(512, 1) void gemm_f16e_dual(
    const f16* __restrict__ sq0, const f16* __restrict__ sq1,
    const f16* __restrict__ wt0, const f16* __restrict__ wt1,
    const f16* __restrict__ ws0, const f16* __restrict__ ws1,
    const float* __restrict__ bt, const float* __restrict__ bs,
    f16* __restrict__ cc0, f16* __restrict__ cc1)
{
    extern __shared__ char smem[];
    const int z = blockIdx.z;
    const f16* Ah = z ? sq0 + 2560 : sq0;
    const f16* Am = z ? sq1 + 2560 : sq1;
    const f16* Wh = z ? ws0 : wt0;
    const f16* Wm = z ? ws1 : wt1;
    const float* b = z ? bs : bt;
    f16* Ch = z ? cc0 + 260 : cc0;
    f16* Cm = z ? cc1 + 260 : cc1;
    gemm_body<0>(Ah, Am, SEQC, Wh, Wm, 512, b, Ch, Cm, nullptr,
                 448, 128, 8, blockIdx.y * 128, 0, smem_u32(smem));
}

// ---------------- pre-split kernels ----------------
__global__ void split_seq2_kernel(const float* __restrict__ seq,
                                  f16* __restrict__ ph, f16* __restrict__ pm)
{
    const long long t = (long long)blockIdx.x * blockDim.x + threadIdx.x;
    const long long total = (long long)MROWS * SEQC / 8;
    if (t >= total) return;
    const long long e = t * 8;
    const int mr = (int)(e / SEQC);
    const int c0 = (int)(e % SEQC);
    const int src = (c0 < 2560) ? c0 : c0 + 4;
    const float4 v0 = *(const float4*)(seq + (size_t)mr * 3076 + src);
    const float4 v1 = *(const float4*)(seq + (size_t)mr * 3076 + src + 4);
    const float v[8] = {v0.x, v0.y, v0.z, v0.w, v1.x, v1.y, v1.z, v1.w};
    f16 h[8], m[8];
#pragma unroll
    for (int i = 0; i < 8; i++) f16_split2(v[i], h[i], m[i]);
    const size_t d = (size_t)mr * SEQC + c0;
    *(uint4*)(ph + d) = *(uint4*)h;
    *(uint4*)(pm + d) = *(uint4*)m;
}

struct WSplitArgs {
    const float* src[6];
    int N[6], K[6], Kp[6];
    int off[6];
    int cum[7];
};
__global__ void split_w_all_kernel(WSplitArgs a,
                                   f16* __restrict__ ph, f16* __restrict__ pm)
{
    const int i = blockIdx.x * blockDim.x + threadIdx.x;
    if (i >= a.cum[6]) return;
    int s = 0;
#pragma unroll
    for (int j = 1; j < 6; ++j) s += (i >= a.cum[j]);
    const int li = i - a.cum[s];
    const int n = li / a.Kp[s], k = li % a.Kp[s];
    const float v = (k < a.K[s]) ? a.src[s][(size_t)n * a.K[s] + k] : 0.0f;
    f16 h, m;
    f16_split2(v, h, m);
    const size_t d = (size_t)a.off[s] + li;
    ph[d] = h; pm[d] = m;
}

__global__ void pos_pad2_kernel(const float* __restrict__ seq,
                                f16* __restrict__ ph, f16* __restrict__ pm)
{
    const int i = blockIdx.x * blockDim.x + threadIdx.x;
    if (i >= MROWS * 64) return;
    const int mr = i >> 6, j = i & 63;
    float v = 0.0f;
    int col;
    if (j < 4) { v = fmaxf(seq[(size_t)mr * 3076 + 2560 + j], 0.0f); col = 256 + j; }
    else       { col = 384 + j; }
    f16 h, m;
    f16_split2(v, h, m);
    const size_t d = (size_t)mr * 448 + col;
    ph[d] = h; pm[d] = m;
}

// ---------------- Sinkhorn ----------------
__global__ __launch_bounds__(512) void sinkhorn_kernel(
    const float* __restrict__ logits, float* __restrict__ out)
{
    __shared__ float X[36][37];
    __shared__ float red[36];
    const int b = blockIdx.x;
    const int t = threadIdx.x;
    const float* src = logits + (size_t)b * 1296;

    for (int i = t; i < 1296; i += 512)
        X[i / 36][i % 36] = expf(src[i] * TAU_INV);
    __syncthreads();

    for (int it = 0; it < 20; ++it) {
        if (t < 36) {
            float mx = -INFINITY;
#pragma unroll
            for (int c = 0; c < 36; c++) mx = fmaxf(mx, X[t][c]);
            float s = 0.0f;
#pragma unroll
            for (int c = 0; c < 36; c++) s += expf(X[t][c] - mx);
            red[t] = mx + logf(s);
        }
        __syncthreads();
        for (int i = t; i < 1296; i += 512) X[i / 36][i % 36] -= red[i / 36];
        __syncthreads();
        if (t < 36) {
            float mx = -INFINITY;
#pragma unroll
            for (int r = 0; r < 36; r++) mx = fmaxf(mx, X[r][t]);
            float s = 0.0f;
#pragma unroll
            for (int r = 0; r < 36; r++) s += expf(X[r][t] - mx);
            red[t] = mx + logf(s);
        }
        __syncthreads();
        for (int i = t; i < 1296; i += 512) X[i / 36][i % 36] -= red[i % 36];
        __syncthreads();
    }
    for (int i = t; i < 1296; i += 512)
        out[(size_t)b * 1296 + i] = expf(X[i / 36][i % 36]);
}

// ---------------- host ----------------
extern "C" void kernel_launch(void* const* d_in, const int* in_sizes, int n_in,
                              void* d_out, int out_size)
{
    const float* seq   = (const float*)d_in[0];
    const float* W1t_w = (const float*)d_in[1];
    const float* W1t_b = (const float*)d_in[2];
    const float* W1v_w = (const float*)d_in[3];
    const float* W1v_b = (const float*)d_in[4];
    const float* W2v_w = (const float*)d_in[5];
    const float* W2v_b = (const float*)d_in[6];
    const float* W1s_w = (const float*)d_in[7];
    const float* W1s_b = (const float*)d_in[8];
    const float* Wfp_w = (const float*)d_in[9];
    const float* Wfp_b = (const float*)d_in[10];
    const float* Wfc_w = (const float*)d_in[11];
    const float* Wfc_b = (const float*)d_in[12];
    float* out = (float*)d_out;

    f16 *sq[2], *xv[2], *cc[2], *a3[2], *wp[2];
    float* logits;
    {
        f16* p;
        cudaGetSymbolAddress((void**)&p, g_seqP);
        sq[0] = p; sq[1] = p + (size_t)MROWS * SEQC;
        cudaGetSymbolAddress((void**)&p, g_xvP);
        xv[0] = p; xv[1] = p + (size_t)MROWS * 512;
        cudaGetSymbolAddress((void**)&p, g_ccP);
        cc[0] = p; cc[1] = p + (size_t)MROWS * 448;
        cudaGetSymbolAddress((void**)&p, g_a3P);
        a3[0] = p; a3[1] = p + (size_t)MROWS * 256;
        cudaGetSymbolAddress((void**)&p, g_wP);
        const size_t wsz = 128*512 + 512*2048 + 128*512 + 128*512 + 256*448 + 36*256;
        wp[0] = p; wp[1] = p + wsz;
        cudaGetSymbolAddress((void**)&logits, g_logits);
    }

    cudaFuncSetAttribute(gemm_f16e<0>, cudaFuncAttributeMaxDynamicSharedMemorySize, GEMM_SMEM);
    cudaFuncSetAttribute(gemm_f16e<1>, cudaFuncAttributeMaxDynamicSharedMemorySize, GEMM_SMEM);
    cudaFuncSetAttribute(gemm_f16e_dual, cudaFuncAttributeMaxDynamicSharedMemorySize, GEMM_SMEM);

    cudaStream_t s1;
    cudaStreamCreateWithFlags(&s1, cudaStreamNonBlocking);
    cudaEvent_t e_fork, e_w, e_seq, e_join;
    cudaEventCreateWithFlags(&e_fork, cudaEventDisableTiming);
    cudaEventCreateWithFlags(&e_w,    cudaEventDisableTiming);
    cudaEventCreateWithFlags(&e_seq,  cudaEventDisableTiming);
    cudaEventCreateWithFlags(&e_join, cudaEventDisableTiming);

    // ---- fork ----
    cudaEventRecord(e_fork, 0);
    cudaStreamWaitEvent(s1, e_fork, 0);

    // side: weight splits + pos/pad
    {
        WSplitArgs a;
        const float* srcs[6] = {W1t_w, W1v_w, W2v_w, W1s_w, Wfp_w, Wfc_w};
        const int Ns[6]  = {128, 512, 128, 128, 256, 36};
        const int Ks[6]  = {512, 2048, 512, 512, 388, 256};
        const int Kps[6] = {512, 2048, 512, 512, 448, 256};
        const int offs[6] = {WOFF_TXT, WOFF_VIS1, WOFF_VIS2, WOFF_SEN, WOFF_FCP, WOFF_FC};
        int c = 0;
        for (int j = 0; j < 6; ++j) {
            a.src[j] = srcs[j]; a.N[j] = Ns[j]; a.K[j] = Ks[j]; a.Kp[j] = Kps[j];
            a.off[j] = offs[j]; a.cum[j] = c; c += Ns[j] * Kps[j];
        }
        a.cum[6] = c;
        split_w_all_kernel<<<(c + 255) / 256, 256, 0, s1>>>(a, wp[0], wp[1]);
    }
    cudaEventRecord(e_w, s1);
    pos_pad2_kernel<<<(MROWS * 64 + 255) / 256, 256, 0, s1>>>(seq, cc[0], cc[1]);

    // main: seq split
    {
        const long long n = (long long)MROWS * SEQC / 8;
        split_seq2_kernel<<<(unsigned)((n + 255) / 256), 256>>>(seq, sq[0], sq[1]);
    }
    cudaEventRecord(e_seq, 0);
    cudaStreamWaitEvent(0, e_w, 0);

    const int mT = MROWS / 128;   // 144

    // main: vis1
    gemm_f16e<0><<<dim3(4, mT), 512, GEMM_SMEM>>>(
        sq[0] + 512, sq[1] + 512, SEQC,
        wp[0] + WOFF_VIS1, wp[1] + WOFF_VIS1, 2048, W1v_b,
        xv[0], xv[1], nullptr, 512, 512, 32);

    // side: txt + sen fused (overlap vis1)
    cudaStreamWaitEvent(s1, e_seq, 0);
    gemm_f16e_dual<<<dim3(1, mT, 2), 512, GEMM_SMEM, s1>>>(
        sq[0], sq[1],
        wp[0] + WOFF_TXT, wp[1] + WOFF_TXT,
        wp[0] + WOFF_SEN, wp[1] + WOFF_SEN,
        W1t_b, W1s_b, cc[0], cc[1]);
    cudaEventRecord(e_join, s1);
    cudaStreamWaitEvent(0, e_join, 0);

    // main: vis2 -> fcp -> fc -> sinkhorn
    gemm_f16e<0><<<dim3(1, mT), 512, GEMM_SMEM>>>(
        xv[0], xv[1], 512,
        wp[0] + WOFF_VIS2, wp[1] + WOFF_VIS2, 512, W2v_b,
        cc[0] + 128, cc[1] + 128, nullptr, 448, 128, 8);
    gemm_f16e<0><<<dim3(2, mT), 512, GEMM_SMEM>>>(
        cc[0], cc[1], 448,
        wp[0] + WOFF_FCP, wp[1] + WOFF_FCP, 448, Wfp_b,
        a3[0], a3[1], nullptr, 256, 256, 7);
    gemm_f16e<1><<<dim3(1, mT), 512, GEMM_SMEM>>>(
        a3[0], a3[1], 256,
        wp[0] + WOFF_FC, wp[1] + WOFF_FC, 256, Wfc_b,
        nullptr, nullptr, logits, 36, 36, 4);

    sinkhorn_kernel<<<512, 512>>>(logits, out);
}